// round 14
// baseline (speedup 1.0000x reference)
#include <cuda_runtime.h>
#include <cuda_fp16.h>
#include <math.h>
#include <cstdint>

#define DIMM   256
#define TT     8192
#define BB     4
#define HEADSN 8
#define DH     32
#define NB     128
#define BUCKET 64
#define FFD    1024
#define DEPTHN 6
#define MROWS  (BB*TT)
#define BHN    (BB*HEADSN)
#define QKVD   768
#define NBK    (BB*NB)

// ======================= static device scratch =======================
__device__ float g_y  [MROWS*DIMM];
__device__ __half g_qkv[MROWS*QKVD];          // also reused as fp32 final-LN scratch
__device__ __half g_h [MROWS*DIMM];
__device__ __half g_o [MROWS*DIMM];
__device__ __half g_wqkv[DEPTHN*QKVD*DIMM];
__device__ __half g_wo  [DEPTHN*DIMM*DIMM];
__device__ __half g_w1  [DEPTHN*DIMM*FFD];
__device__ __half g_w2  [DEPTHN*FFD*DIMM];
__device__ float g_hmean[NBK*DIMM];
__device__ float g_sq[BHN*NB*DH];
__device__ float g_sk[BHN*NB*DH];
__device__ float g_top[BHN*NB];
__device__ int   g_idx[BHN*NB];

// ======================= helpers =======================
__device__ __forceinline__ uint32_t smem_u32(const void* p) {
    uint32_t a;
    asm("{ .reg .u64 t; cvta.to.shared.u64 t, %1; cvt.u32.u64 %0, t; }" : "=r"(a) : "l"(p));
    return a;
}
__device__ __forceinline__ uint32_t pack_half2(float a, float b) {
    __half2 h = __floats2half2_rn(a, b);
    return *reinterpret_cast<uint32_t*>(&h);
}

#define MMA_F16(c, a, b0, b1) \
    asm volatile("mma.sync.aligned.m16n8k16.row.col.f32.f16.f16.f32 " \
        "{%0,%1,%2,%3}, {%4,%5,%6,%7}, {%8,%9}, {%0,%1,%2,%3};" \
        : "+f"((c)[0]), "+f"((c)[1]), "+f"((c)[2]), "+f"((c)[3]) \
        : "r"((a)[0]), "r"((a)[1]), "r"((a)[2]), "r"((a)[3]), "r"(b0), "r"(b1))

#define LDSM_X4(r, addr) \
    asm volatile("ldmatrix.sync.aligned.m8n8.x4.shared.b16 {%0,%1,%2,%3}, [%4];" \
        : "=r"((r)[0]), "=r"((r)[1]), "=r"((r)[2]), "=r"((r)[3]) : "r"(addr))

#define LDSM_X4_T(r, addr) \
    asm volatile("ldmatrix.sync.aligned.m8n8.x4.trans.shared.b16 {%0,%1,%2,%3}, [%4];" \
        : "=r"((r)[0]), "=r"((r)[1]), "=r"((r)[2]), "=r"((r)[3]) : "r"(addr))

#define CP_ASYNC16(dst, src) \
    asm volatile("cp.async.cg.shared.global [%0], [%1], 16;" :: "r"(dst), "l"(src))
#define CP_COMMIT()  asm volatile("cp.async.commit_group;" ::: "memory")
#define CP_WAIT(n)   asm volatile("cp.async.wait_group %0;" :: "n"(n) : "memory")

// ======================= small kernels =======================
__global__ void pos_add_kernel(const float* __restrict__ x, const float* __restrict__ pe0,
                               const float* __restrict__ pe1, float* __restrict__ y) {
    __shared__ float tile[32][33];
    int b = blockIdx.z, d0 = blockIdx.y * 32, t0 = blockIdx.x * 32;
    int tx = threadIdx.x, ty = threadIdx.y;
    const float* xb = x + (size_t)b * DIMM * TT;
    #pragma unroll
    for (int i = 0; i < 32; i += 8)
        tile[ty + i][tx] = xb[(size_t)(d0 + ty + i) * TT + t0 + tx];
    __syncthreads();
    float* yb = y + (size_t)b * TT * DIMM;
    #pragma unroll
    for (int i = 0; i < 32; i += 8) {
        int t = t0 + ty + i, d = d0 + tx;
        yb[(size_t)t * DIMM + d] =
            tile[tx][ty + i] + pe0[(size_t)(t >> 6) * DIMM + d] + pe1[(size_t)(t & 63) * DIMM + d];
    }
}

__global__ void out_transpose_kernel(const float* __restrict__ hin, float* __restrict__ out) {
    __shared__ float tile[32][33];
    int b = blockIdx.z, d0 = blockIdx.y * 32, t0 = blockIdx.x * 32;
    int tx = threadIdx.x, ty = threadIdx.y;
    const float* hb = hin + (size_t)b * TT * DIMM;
    #pragma unroll
    for (int i = 0; i < 32; i += 8)
        tile[ty + i][tx] = hb[(size_t)(t0 + ty + i) * DIMM + d0 + tx];
    __syncthreads();
    float* ob = out + (size_t)b * DIMM * TT;
    #pragma unroll
    for (int i = 0; i < 32; i += 8)
        ob[(size_t)(d0 + ty + i) * TT + t0 + tx] = tile[tx][ty + i];
}

// LN -> fp32 (final)
__global__ void ln_kernel(const float* __restrict__ in, float* __restrict__ out,
                          const float* __restrict__ g, const float* __restrict__ b) {
    int row = blockIdx.x * 8 + (threadIdx.x >> 5);
    int lane = threadIdx.x & 31;
    const float* r = in + (size_t)row * DIMM;
    float v[8], s = 0.f;
    #pragma unroll
    for (int i = 0; i < 8; i++) { v[i] = r[lane + i * 32]; s += v[i]; }
    #pragma unroll
    for (int off = 16; off; off >>= 1) s += __shfl_xor_sync(0xffffffffu, s, off);
    float m = s * (1.0f / DIMM), var = 0.f;
    #pragma unroll
    for (int i = 0; i < 8; i++) { float d = v[i] - m; var += d * d; }
    #pragma unroll
    for (int off = 16; off; off >>= 1) var += __shfl_xor_sync(0xffffffffu, var, off);
    float inv = rsqrtf(var * (1.0f / DIMM) + 1e-5f);
    float* o = out + (size_t)row * DIMM;
    #pragma unroll
    for (int i = 0; i < 8; i++) {
        int c = lane + i * 32;
        o[c] = (v[i] - m) * inv * g[c] + b[c];
    }
}

// LN1 fused: 256 threads, 8 warps x 8 rows = 64 rows = 1 bucket
__global__ void ln1_fused_kernel(const float* __restrict__ y, __half* __restrict__ oh,
                                 const float* __restrict__ g, const float* __restrict__ b,
                                 float* __restrict__ hmean) {
    __shared__ float acc[8][DIMM];
    int bu = blockIdx.x;
    int warp = threadIdx.x >> 5, lane = threadIdx.x & 31;
    float la[8];
    #pragma unroll
    for (int i = 0; i < 8; i++) la[i] = 0.f;
    for (int rr = 0; rr < 8; rr++) {
        int row = bu * BUCKET + warp * 8 + rr;
        const float* r = y + (size_t)row * DIMM;
        float v[8], s = 0.f;
        #pragma unroll
        for (int i = 0; i < 8; i++) { v[i] = r[lane + i * 32]; s += v[i]; }
        #pragma unroll
        for (int off = 16; off; off >>= 1) s += __shfl_xor_sync(0xffffffffu, s, off);
        float m = s * (1.0f / DIMM), var = 0.f;
        #pragma unroll
        for (int i = 0; i < 8; i++) { float d = v[i] - m; var += d * d; }
        #pragma unroll
        for (int off = 16; off; off >>= 1) var += __shfl_xor_sync(0xffffffffu, var, off);
        float inv = rsqrtf(var * (1.0f / DIMM) + 1e-5f);
        #pragma unroll
        for (int i = 0; i < 8; i++) {
            int c = lane + i * 32;
            float val = (v[i] - m) * inv * g[c] + b[c];
            oh[(size_t)row * DIMM + c] = __float2half(val);
            la[i] += val;
        }
    }
    #pragma unroll
    for (int i = 0; i < 8; i++) acc[warp][lane + i * 32] = la[i];
    __syncthreads();
    for (int c = threadIdx.x; c < DIMM; c += 256) {
        float s = 0.f;
        #pragma unroll
        for (int w = 0; w < 8; w++) s += acc[w][c];
        hmean[(size_t)bu * DIMM + c] = s * (1.0f / BUCKET);
    }
}

__global__ void route_gemm_kernel(const float* __restrict__ hmean,
                                  const float* __restrict__ Wq, const float* __restrict__ Wkv) {
    __shared__ float hm[DIMM];
    int row = blockIdx.x;
    int sel = blockIdx.y;
    int c = threadIdx.x;
    hm[c] = hmean[(size_t)row * DIMM + c];
    __syncthreads();
    const float* W = sel ? Wkv : Wq;
    int ldw = sel ? 2 * DIMM : DIMM;
    float a = 0.f;
    #pragma unroll 8
    for (int k = 0; k < DIMM; k++) a = fmaf(hm[k], W[(size_t)k * ldw + c], a);
    int b = row >> 7, u = row & 127;
    int h = c >> 5, e = c & 31;
    size_t dst = (((size_t)(b * HEADSN + h)) * NB + u) * DH + e;
    if (sel) g_sk[dst] = a; else g_sq[dst] = a;
}

__global__ void wconv_kernel(const float* __restrict__ W, __half* __restrict__ T,
                             int K, int N, size_t lstride) {
    __shared__ float t[32][33];
    int l = blockIdx.z;
    const float* Wl = W + (size_t)l * K * N;
    size_t ob = (size_t)l * lstride;
    int n0 = blockIdx.x * 32, k0 = blockIdx.y * 32;
    int tx = threadIdx.x, ty = threadIdx.y;
    #pragma unroll
    for (int i = 0; i < 32; i += 8)
        t[ty + i][tx] = Wl[(size_t)(k0 + ty + i) * N + n0 + tx];
    __syncthreads();
    #pragma unroll
    for (int i = 0; i < 32; i += 8)
        T[ob + (size_t)(n0 + ty + i) * K + k0 + tx] = __float2half(t[tx][ty + i]);
}

// ======================= pipelined fp16 HMMA GEMM (128x128) =======================
#define AH_OFF 0
#define BH_OFF 16384
#define STAGE_SZ 32768
#define NSTAGE 3
#define GEMM_SMEM (NSTAGE*STAGE_SZ)

__device__ __forceinline__ void gemm_load_stage(
    uint32_t sb, int stg, int tid, int k0,
    const __half* __restrict__ Ah, int lda,
    const __half* __restrict__ Bh, int ldb,
    int m0, int n0) {
    uint32_t base = sb + stg * STAGE_SZ;
    #pragma unroll
    for (int p = 0; p < 4; ++p) {
        int lin = p * 256 + tid;
        int r = lin >> 3, kb = lin & 7;
        uint32_t soff = (uint32_t)(r * 128 + ((kb ^ (r & 7)) << 4));
        CP_ASYNC16(base + AH_OFF + soff, Ah + (size_t)(m0 + r) * lda + k0 + kb * 8);
        CP_ASYNC16(base + BH_OFF + soff, Bh + (size_t)(n0 + r) * ldb + k0 + kb * 8);
    }
}

__global__ __launch_bounds__(256)
void hmma_gemm(const __half* __restrict__ Ah, int lda,
               const __half* __restrict__ Bh, int ldb,
               const float* __restrict__ bias, const float* __restrict__ resid,
               float* __restrict__ Cf, __half* __restrict__ Ch,
               int ldc, int K, int gelu) {
    extern __shared__ char smem[];
    uint32_t sb = smem_u32(smem);
    int tid = threadIdx.x;
    int lane = tid & 31, wid = tid >> 5;
    int wm = wid >> 2, wn = wid & 3;
    int m0 = blockIdx.y * 128, n0 = blockIdx.x * 128;

    float acc[4][4][4];
    #pragma unroll
    for (int i = 0; i < 4; i++)
        #pragma unroll
        for (int j = 0; j < 4; j++)
            #pragma unroll
            for (int k = 0; k < 4; k++) acc[i][j][k] = 0.f;

    int a_row = (lane & 15);
    int a_kh  = (lane >> 4);
    int b_sub = (lane >> 3);
    int b_row = ((b_sub >> 1) << 3) + (lane & 7);
    int b_kh  = (b_sub & 1);

    const int nch = K >> 6;
    gemm_load_stage(sb, 0, tid, 0, Ah, lda, Bh, ldb, m0, n0);
    CP_COMMIT();
    if (nch > 1) {
        gemm_load_stage(sb, 1, tid, 64, Ah, lda, Bh, ldb, m0, n0);
        CP_COMMIT();
    }

    for (int ch = 0; ch < nch; ++ch) {
        if (ch + 2 < nch) {
            gemm_load_stage(sb, (ch + 2) % NSTAGE, tid, (ch + 2) << 6, Ah, lda, Bh, ldb, m0, n0);
            CP_COMMIT();
            CP_WAIT(2);
        } else if (ch + 1 < nch) {
            CP_WAIT(1);
        } else {
            CP_WAIT(0);
        }
        __syncthreads();

        uint32_t stg = sb + (ch % NSTAGE) * STAGE_SZ;
        #pragma unroll
        for (int ks = 0; ks < 4; ++ks) {
            uint32_t bhf[4][2];
            #pragma unroll
            for (int pair = 0; pair < 2; ++pair) {
                int row = wn * 32 + pair * 16 + b_row;
                int kb = ks * 2 + b_kh;
                uint32_t addr = stg + (uint32_t)(row * 128 + ((kb ^ (row & 7)) << 4));
                uint32_t rg[4];
                LDSM_X4(rg, addr + BH_OFF);
                bhf[pair * 2][0] = rg[0]; bhf[pair * 2][1] = rg[1];
                bhf[pair * 2 + 1][0] = rg[2]; bhf[pair * 2 + 1][1] = rg[3];
            }
            #pragma unroll
            for (int mt = 0; mt < 4; ++mt) {
                int row = wm * 64 + mt * 16 + a_row;
                int kb = ks * 2 + a_kh;
                uint32_t addr = stg + (uint32_t)(row * 128 + ((kb ^ (row & 7)) << 4));
                uint32_t ah[4];
                LDSM_X4(ah, addr + AH_OFF);
                #pragma unroll
                for (int nt = 0; nt < 4; ++nt)
                    MMA_F16(acc[mt][nt], ah, bhf[nt][0], bhf[nt][1]);
            }
        }
        __syncthreads();
    }

    int rbase = m0 + wm * 64 + (lane >> 2);
    int cbase = n0 + wn * 32 + (lane & 3) * 2;
    #pragma unroll
    for (int mt = 0; mt < 4; ++mt) {
        #pragma unroll
        for (int nt = 0; nt < 4; ++nt) {
            #pragma unroll
            for (int half = 0; half < 2; ++half) {
                int gm = rbase + mt * 16 + half * 8;
                int gn = cbase + nt * 8;
                float v0 = acc[mt][nt][half * 2 + 0];
                float v1 = acc[mt][nt][half * 2 + 1];
                if (bias) { v0 += bias[gn]; v1 += bias[gn + 1]; }
                if (gelu) {
                    v0 = 0.5f * v0 * (1.0f + erff(v0 * 0.70710678118654752f));
                    v1 = 0.5f * v1 * (1.0f + erff(v1 * 0.70710678118654752f));
                }
                size_t go = (size_t)gm * ldc + gn;
                if (resid) { v0 += resid[go]; v1 += resid[go + 1]; }
                if (Cf) {
                    *reinterpret_cast<float2*>(Cf + go) = make_float2(v0, v1);
                } else {
                    *reinterpret_cast<__half2*>(Ch + go) = __floats2half2_rn(v0, v1);
                }
            }
        }
    }
}

// ======================= fused MLP with in-kernel LN2 =======================
// y tile (64x256 fp32) -> LN2 -> fp16 h planes in smem -> y += gelu(h@W1+b1)@W2 + b2
#define FH_OFF  0
#define FP_OFF  32768
#define FW1_OFF 40960
#define FW2_OFF 106496
#define FF_SMEM 172032

__device__ __forceinline__ void ff_load_w(uint32_t sb, int buf, int tid, int c,
                                          const __half* __restrict__ W1T,
                                          const __half* __restrict__ W2T) {
    #pragma unroll
    for (int p = 0; p < 8; ++p) {
        int lin = p * 256 + tid;
        int r = lin >> 5;
        int rest = lin & 31;
        int pl = rest >> 3, kb = rest & 7;
        uint32_t dst = sb + FW1_OFF + buf * 32768 +
                       (uint32_t)(pl * 8192 + r * 128 + ((kb ^ (r & 7)) << 4));
        CP_ASYNC16(dst, W1T + (size_t)(c * 64 + r) * DIMM + pl * 64 + kb * 8);
    }
    #pragma unroll
    for (int p = 0; p < 8; ++p) {
        int lin = p * 256 + tid;
        int r = lin >> 3, kb = lin & 7;
        uint32_t dst = sb + FW2_OFF + buf * 32768 +
                       (uint32_t)(r * 128 + ((kb ^ (r & 7)) << 4));
        CP_ASYNC16(dst, W2T + (size_t)r * FFD + c * 64 + kb * 8);
    }
}

__global__ __launch_bounds__(256)
void ff_fused(const float* __restrict__ yin,
              const float* __restrict__ lg, const float* __restrict__ lb,
              const __half* __restrict__ W1T, const float* __restrict__ b1,
              const __half* __restrict__ W2T, const float* __restrict__ b2,
              float* __restrict__ y) {
    extern __shared__ char smem[];
    uint32_t sb = smem_u32(smem);
    int tid = threadIdx.x;
    int lane = tid & 31, wid = tid >> 5;
    int wm = wid >> 2, wn = wid & 3;      // 2 x 4
    int m0 = blockIdx.x * 64;

    int a_row = (lane & 15);
    int a_kh  = (lane >> 4);
    int b_sub = (lane >> 3);
    int b_row = ((b_sub >> 1) << 3) + (lane & 7);
    int b_kh  = (b_sub & 1);

    float acc_out[2][8][4];
    #pragma unroll
    for (int i = 0; i < 2; i++)
        #pragma unroll
        for (int j = 0; j < 8; j++)
            #pragma unroll
            for (int k = 0; k < 4; k++) acc_out[i][j][k] = 0.f;

    // kick off W prefetch first (overlaps with LN below)
    ff_load_w(sb, 0, tid, 0, W1T, W2T);
    CP_COMMIT();
    ff_load_w(sb, 1, tid, 1, W1T, W2T);
    CP_COMMIT();

    // ---- LN2 fused prologue: y -> fp16 h planes in smem ----
    {
        // per-thread columns: c = lane*8 .. lane*8+7; gamma/beta hoisted
        float gv[8], bv[8];
        #pragma unroll
        for (int j = 0; j < 8; j++) { gv[j] = lg[lane * 8 + j]; bv[j] = lb[lane * 8 + j]; }
        int pl = lane >> 3, kb = lane & 7;
        for (int rr = 0; rr < 8; rr++) {
            int r = wid * 8 + rr;                      // 0..63
            const float* yr = yin + (size_t)(m0 + r) * DIMM + lane * 8;
            float4 f0 = *reinterpret_cast<const float4*>(yr);
            float4 f1 = *reinterpret_cast<const float4*>(yr + 4);
            float v[8] = {f0.x, f0.y, f0.z, f0.w, f1.x, f1.y, f1.z, f1.w};
            float s = 0.f;
            #pragma unroll
            for (int j = 0; j < 8; j++) s += v[j];
            #pragma unroll
            for (int off = 16; off; off >>= 1) s += __shfl_xor_sync(0xffffffffu, s, off);
            float m = s * (1.0f / DIMM), var = 0.f;
            #pragma unroll
            for (int j = 0; j < 8; j++) { float d = v[j] - m; var += d * d; }
            #pragma unroll
            for (int off = 16; off; off >>= 1) var += __shfl_xor_sync(0xffffffffu, var, off);
            float inv = rsqrtf(var * (1.0f / DIMM) + 1e-5f);
            uint32_t pk[4];
            #pragma unroll
            for (int j = 0; j < 4; j++) {
                float v0 = (v[2 * j]     - m) * inv * gv[2 * j]     + bv[2 * j];
                float v1 = (v[2 * j + 1] - m) * inv * gv[2 * j + 1] + bv[2 * j + 1];
                pk[j] = pack_half2(v0, v1);
            }
            uint32_t addr = sb + FH_OFF +
                (uint32_t)(pl * 8192 + r * 128 + ((kb ^ (r & 7)) << 4));
            asm volatile("st.shared.v4.b32 [%0], {%1,%2,%3,%4};"
                :: "r"(addr), "r"(pk[0]), "r"(pk[1]), "r"(pk[2]), "r"(pk[3]));
        }
    }

    for (int c = 0; c < 16; ++c) {
        int buf = c & 1;
        if (c < 15) CP_WAIT(1);
        else        CP_WAIT(0);
        __syncthreads();   // chunk c weights + (c==0: LN stores) ready

        // ---- gemm1: P_raw(64x64) = h(64x256) @ W1chunk^T ----
        float acc1[2][2][4];
        #pragma unroll
        for (int i = 0; i < 2; i++)
            #pragma unroll
            for (int j = 0; j < 2; j++)
                #pragma unroll
                for (int k = 0; k < 4; k++) acc1[i][j][k] = 0.f;
        uint32_t w1b = sb + FW1_OFF + buf * 32768;
        #pragma unroll
        for (int ks = 0; ks < 16; ++ks) {
            int pl = ks >> 2, k2 = ks & 3;
            uint32_t rgB[4];
            {
                int row = wn * 16 + b_row;
                int kb = k2 * 2 + b_kh;
                LDSM_X4(rgB, w1b + (uint32_t)(pl * 8192 + row * 128 + ((kb ^ (row & 7)) << 4)));
            }
            #pragma unroll
            for (int mt = 0; mt < 2; ++mt) {
                int row = wm * 32 + mt * 16 + a_row;
                int kb = k2 * 2 + a_kh;
                uint32_t ah[4];
                LDSM_X4(ah, sb + FH_OFF + (uint32_t)(pl * 8192 + row * 128 + ((kb ^ (row & 7)) << 4)));
                MMA_F16(acc1[mt][0], ah, rgB[0], rgB[1]);
                MMA_F16(acc1[mt][1], ah, rgB[2], rgB[3]);
            }
        }

        // ---- bias1 + gelu, store P ----
        #pragma unroll
        for (int mt = 0; mt < 2; ++mt) {
            #pragma unroll
            for (int nt = 0; nt < 2; ++nt) {
                #pragma unroll
                for (int half = 0; half < 2; ++half) {
                    int pr = wm * 32 + mt * 16 + half * 8 + (lane >> 2);
                    int pc = wn * 16 + nt * 8 + (lane & 3) * 2;
                    float v0 = acc1[mt][nt][half * 2 + 0] + b1[c * 64 + pc];
                    float v1 = acc1[mt][nt][half * 2 + 1] + b1[c * 64 + pc + 1];
                    v0 = 0.5f * v0 * (1.0f + erff(v0 * 0.70710678118654752f));
                    v1 = 0.5f * v1 * (1.0f + erff(v1 * 0.70710678118654752f));
                    uint32_t addr = sb + FP_OFF +
                        (uint32_t)(pr * 128 + (((pc >> 3) ^ (pr & 7)) << 4) + (pc & 7) * 2);
                    asm volatile("st.shared.b32 [%0], %1;" :: "r"(addr), "r"(pack_half2(v0, v1)));
                }
            }
        }
        __syncthreads();

        // ---- gemm2: acc_out += P(64x64) @ W2chunk^T ----
        uint32_t w2b = sb + FW2_OFF + buf * 32768;
        #pragma unroll
        for (int ks = 0; ks < 4; ++ks) {
            uint32_t bfr[8][2];
            #pragma unroll
            for (int pair = 0; pair < 4; ++pair) {
                int row = wn * 64 + pair * 16 + b_row;
                int kb = ks * 2 + b_kh;
                uint32_t rg[4];
                LDSM_X4(rg, w2b + (uint32_t)(row * 128 + ((kb ^ (row & 7)) << 4)));
                bfr[pair * 2][0] = rg[0]; bfr[pair * 2][1] = rg[1];
                bfr[pair * 2 + 1][0] = rg[2]; bfr[pair * 2 + 1][1] = rg[3];
            }
            #pragma unroll
            for (int mt = 0; mt < 2; ++mt) {
                int row = wm * 32 + mt * 16 + a_row;
                int kb = ks * 2 + a_kh;
                uint32_t ah[4];
                LDSM_X4(ah, sb + FP_OFF + (uint32_t)(row * 128 + ((kb ^ (row & 7)) << 4)));
                #pragma unroll
                for (int nt = 0; nt < 8; ++nt)
                    MMA_F16(acc_out[mt][nt], ah, bfr[nt][0], bfr[nt][1]);
            }
        }
        __syncthreads();

        if (c + 2 < 16) {
            ff_load_w(sb, buf, tid, c + 2, W1T, W2T);
            CP_COMMIT();
        }
    }

    // ---- epilogue: + bias2 + residual y -> y ----
    int rbase = m0 + wm * 32 + (lane >> 2);
    int cbase = wn * 64 + (lane & 3) * 2;
    #pragma unroll
    for (int mt = 0; mt < 2; ++mt) {
        #pragma unroll
        for (int nt = 0; nt < 8; ++nt) {
            #pragma unroll
            for (int half = 0; half < 2; ++half) {
                int gm = rbase + mt * 16 + half * 8;
                int gn = cbase + nt * 8;
                size_t go = (size_t)gm * DIMM + gn;
                float v0 = acc_out[mt][nt][half * 2 + 0] + b2[gn]     + y[go];
                float v1 = acc_out[mt][nt][half * 2 + 1] + b2[gn + 1] + y[go + 1];
                *reinterpret_cast<float2*>(y + go) = make_float2(v0, v1);
            }
        }
    }
}

// ======================= attention =======================
__global__ void routing_kernel() {
    int bh = blockIdx.x;
    int i = threadIdx.x;
    __shared__ float ssk[NB][DH];
    const float* base = g_sk + (size_t)bh * NB * DH;
    for (int idx = i; idx < NB * DH; idx += NB) ssk[idx / DH][idx % DH] = base[idx];
    float sq[DH];
    const float* sqp = g_sq + ((size_t)bh * NB + i) * DH;
    #pragma unroll
    for (int e = 0; e < DH; e++) sq[e] = sqp[e];
    __syncthreads();
    const float sc = 0.17677669529663687f * (1.0f / 0.75f);
    float mx = -1e30f; int am = 0;
    for (int j = 0; j < NB; j++) {
        float d = 0.f;
        #pragma unroll
        for (int e = 0; e < DH; e++) d = fmaf(sq[e], ssk[j][e], d);
        d *= sc;
        if (d > mx) { mx = d; am = j; }
    }
    float sum = 0.f;
    for (int j = 0; j < NB; j++) {
        float d = 0.f;
        #pragma unroll
        for (int e = 0; e < DH; e++) d = fmaf(sq[e], ssk[j][e], d);
        sum += expf(d * sc - mx);
    }
    g_top[bh * NB + i] = 1.0f / sum;
    g_idx[bh * NB + i] = am;
}

__global__ __launch_bounds__(128)
void attn_kernel(const __half* __restrict__ qkv, __half* __restrict__ o) {
    __shared__ __half sQ[64 * 40];
    __shared__ __half sK[128 * 40];
    __shared__ __half sV[128 * 40];
    int u = blockIdx.x, bh = blockIdx.y;
    int b = bh >> 3, h = bh & 7;
    int tid = threadIdx.x, lane = tid & 31, warp = tid >> 5;
    float top = g_top[bh * NB + u];
    int ridx = g_idx[bh * NB + u];
    const __half* qg = qkv + ((size_t)(b * TT + u * BUCKET)) * QKVD + h * DH;
    const __half* kgs = qg + 256;
    const __half* kgr = qkv + ((size_t)(b * TT + ridx * BUCKET)) * QKVD + 256 + h * DH;
    uint32_t sqa = smem_u32(sQ), ska = smem_u32(sK), sva = smem_u32(sV);

    #pragma unroll
    for (int i = tid; i < 256; i += 128) {
        int r = i >> 2, cb = i & 3;
        CP_ASYNC16(sqa + r * 80 + cb * 16, qg + (size_t)r * QKVD + cb * 8);
    }
    #pragma unroll
    for (int i = tid; i < 512; i += 128) {
        int r = i >> 2, cb = i & 3;
        const __half* kr = (r < 64) ? kgr + (size_t)r * QKVD : kgs + (size_t)(r - 64) * QKVD;
        CP_ASYNC16(ska + r * 80 + cb * 16, kr + cb * 8);
        CP_ASYNC16(sva + r * 80 + cb * 16, kr + 256 + cb * 8);
    }
    CP_COMMIT(); CP_WAIT(0);
    __syncthreads();

    uint32_t qa[2][4];
    #pragma unroll
    for (int kh = 0; kh < 2; ++kh) {
        uint32_t addr = sqa + (uint32_t)((warp * 16 + (lane & 15)) * 80 + (lane >> 4) * 16 + kh * 32);
        LDSM_X4(qa[kh], addr);
    }

    float acc[16][4];
    #pragma unroll
    for (int t = 0; t < 16; t++)
        #pragma unroll
        for (int j = 0; j < 4; j++) acc[t][j] = 0.f;
    int b_sub = lane >> 3;
    int b_row = ((b_sub >> 1) << 3) + (lane & 7);
    int b_kh  = b_sub & 1;
    #pragma unroll
    for (int pair = 0; pair < 8; ++pair) {
        #pragma unroll
        for (int kh = 0; kh < 2; ++kh) {
            uint32_t addr = ska + (uint32_t)((pair * 16 + b_row) * 80 + kh * 32 + b_kh * 16);
            uint32_t rg[4];
            LDSM_X4(rg, addr);
            MMA_F16(acc[pair * 2],     qa[kh], rg[0], rg[1]);
            MMA_F16(acc[pair * 2 + 1], qa[kh], rg[2], rg[3]);
        }
    }

    const float scale = 0.17677669529663687f;
    #pragma unroll
    for (int t = 0; t < 16; t++) {
        float f = (t < 8) ? scale * top : scale;
        #pragma unroll
        for (int j = 0; j < 4; j++) acc[t][j] *= f;
    }
    float mx0 = -1e30f, mx1 = -1e30f;
    #pragma unroll
    for (int t = 0; t < 16; t++) {
        mx0 = fmaxf(mx0, fmaxf(acc[t][0], acc[t][1]));
        mx1 = fmaxf(mx1, fmaxf(acc[t][2], acc[t][3]));
    }
    #pragma unroll
    for (int off = 1; off < 4; off <<= 1) {
        mx0 = fmaxf(mx0, __shfl_xor_sync(0xffffffffu, mx0, off));
        mx1 = fmaxf(mx1, __shfl_xor_sync(0xffffffffu, mx1, off));
    }
    float s0 = 0.f, s1 = 0.f;
    #pragma unroll
    for (int t = 0; t < 16; t++) {
        acc[t][0] = __expf(acc[t][0] - mx0);
        acc[t][1] = __expf(acc[t][1] - mx0);
        acc[t][2] = __expf(acc[t][2] - mx1);
        acc[t][3] = __expf(acc[t][3] - mx1);
        s0 += acc[t][0] + acc[t][1];
        s1 += acc[t][2] + acc[t][3];
    }
    #pragma unroll
    for (int off = 1; off < 4; off <<= 1) {
        s0 += __shfl_xor_sync(0xffffffffu, s0, off);
        s1 += __shfl_xor_sync(0xffffffffu, s1, off);
    }
    float i0 = 1.0f / s0, i1 = 1.0f / s1;
    #pragma unroll
    for (int t = 0; t < 16; t++) {
        float f0 = (t < 8) ? i0 * top : i0;
        float f1 = (t < 8) ? i1 * top : i1;
        acc[t][0] *= f0; acc[t][1] *= f0;
        acc[t][2] *= f1; acc[t][3] *= f1;
    }

    float out[4][4];
    #pragma unroll
    for (int nt = 0; nt < 4; nt++)
        #pragma unroll
        for (int j = 0; j < 4; j++) out[nt][j] = 0.f;
    int v_row = (lane & 7) + ((lane >> 3) & 1) * 8;
    int v_ch  = (lane >> 4);
    #pragma unroll
    for (int s = 0; s < 8; ++s) {
        uint32_t pa[4];
        pa[0] = pack_half2(acc[2*s][0],   acc[2*s][1]);
        pa[1] = pack_half2(acc[2*s][2],   acc[2*s][3]);
        pa[2] = pack_half2(acc[2*s+1][0], acc[2*s+1][1]);
        pa[3] = pack_half2(acc[2*s+1][2], acc[2*s+1][3]);
        #pragma unroll
        for (int nh = 0; nh < 2; ++nh) {
            uint32_t addr = sva + (uint32_t)((s * 16 + v_row) * 80 + nh * 32 + v_ch * 16);
            uint32_t rg[4];
            LDSM_X4_T(rg, addr);
            MMA_F16(out[nh * 2],     pa, rg[0], rg[1]);
            MMA_F16(out[nh * 2 + 1], pa, rg[2], rg[3]);
        }
    }

    int r0 = warp * 16 + (lane >> 2);
    size_t ob = ((size_t)(b * TT + u * BUCKET + r0)) * DIMM + h * DH;
    #pragma unroll
    for (int nt = 0; nt < 4; ++nt) {
        int col = nt * 8 + (lane & 3) * 2;
        *reinterpret_cast<__half2*>(o + ob + col) = __floats2half2_rn(out[nt][0], out[nt][1]);
        *reinterpret_cast<__half2*>(o + ob + 8 * DIMM + col) = __floats2half2_rn(out[nt][2], out[nt][3]);
    }
}

// ======================= host orchestration =======================
extern "C" void kernel_launch(void* const* d_in, const int* in_sizes, int n_in,
                              void* d_out, int out_size) {
    const float* x     = (const float*)d_in[0];
    const float* pe0   = (const float*)d_in[1];
    const float* pe1   = (const float*)d_in[2];
    const float* ln1_g = (const float*)d_in[3];
    const float* ln1_b = (const float*)d_in[4];
    const float* Wq    = (const float*)d_in[5];
    const float* Wkv   = (const float*)d_in[6];
    const float* Wo    = (const float*)d_in[7];
    const float* bo    = (const float*)d_in[8];
    const float* ln2_g = (const float*)d_in[9];
    const float* ln2_b = (const float*)d_in[10];
    const float* W1    = (const float*)d_in[11];
    const float* b1    = (const float*)d_in[12];
    const float* W2    = (const float*)d_in[13];
    const float* b2    = (const float*)d_in[14];
    const float* gf    = (const float*)d_in[15];
    const float* bf    = (const float*)d_in[16];
    float* out = (float*)d_out;

    cudaFuncSetAttribute(hmma_gemm, cudaFuncAttributeMaxDynamicSharedMemorySize, GEMM_SMEM);
    cudaFuncSetAttribute(ff_fused,  cudaFuncAttributeMaxDynamicSharedMemorySize, FF_SMEM);

    float *y, *hmean;
    __half *qkv, *h, *o;
    __half *wqkv, *wo, *w1, *w2;
    cudaGetSymbolAddress((void**)&y, g_y);
    cudaGetSymbolAddress((void**)&qkv, g_qkv);
    cudaGetSymbolAddress((void**)&hmean, g_hmean);
    cudaGetSymbolAddress((void**)&h, g_h);
    cudaGetSymbolAddress((void**)&o, g_o);
    cudaGetSymbolAddress((void**)&wqkv, g_wqkv);
    cudaGetSymbolAddress((void**)&wo, g_wo);
    cudaGetSymbolAddress((void**)&w1, g_w1);
    cudaGetSymbolAddress((void**)&w2, g_w2);

    dim3 tb(32, 8);
    const size_t QKV_LS = (size_t)QKVD * DIMM;
    wconv_kernel<<<dim3(DIMM / 32,   DIMM / 32, DEPTHN), tb>>>(Wq,  wqkv, DIMM, DIMM, QKV_LS);
    wconv_kernel<<<dim3(2*DIMM / 32, DIMM / 32, DEPTHN), tb>>>(Wkv, wqkv + 256 * DIMM, DIMM, 2*DIMM, QKV_LS);
    wconv_kernel<<<dim3(DIMM / 32,   DIMM / 32, DEPTHN), tb>>>(Wo,  wo, DIMM, DIMM, (size_t)DIMM * DIMM);
    wconv_kernel<<<dim3(FFD / 32,    DIMM / 32, DEPTHN), tb>>>(W1,  w1, DIMM, FFD, (size_t)DIMM * FFD);
    wconv_kernel<<<dim3(DIMM / 32,   FFD / 32,  DEPTHN), tb>>>(W2,  w2, FFD,  DIMM, (size_t)DIMM * FFD);

    dim3 tg(TT / 32, DIMM / 32, BB);
    pos_add_kernel<<<tg, tb>>>(x, pe0, pe1, y);

    for (int L = 0; L < DEPTHN; L++) {
        const float* g1 = ln1_g + (size_t)L * DIMM;
        const float* bb = ln1_b + (size_t)L * DIMM;
        const float* bo_ = bo + (size_t)L * DIMM;
        const float* bb1 = b1 + (size_t)L * FFD;
        const float* bb2 = b2 + (size_t)L * DIMM;
        size_t oqkv = (size_t)L * QKV_LS;
        size_t oo   = (size_t)L * DIMM * DIMM;
        size_t off1 = (size_t)L * DIMM * FFD;

        ln1_fused_kernel<<<NBK, 256>>>(y, h, g1, bb, hmean);
        route_gemm_kernel<<<dim3(NBK, 2), 256>>>(hmean,
            Wq + (size_t)L * DIMM * DIMM, Wkv + (size_t)L * DIMM * 2 * DIMM);
        routing_kernel<<<BHN, NB>>>();
        hmma_gemm<<<dim3(QKVD / 128, MROWS / 128), 256, GEMM_SMEM>>>(h, DIMM,
            wqkv + oqkv, DIMM, nullptr, nullptr, nullptr, qkv, QKVD, DIMM, 0);
        attn_kernel<<<dim3(NB, BHN), 128>>>(qkv, o);
        hmma_gemm<<<dim3(2, MROWS / 128), 256, GEMM_SMEM>>>(o, DIMM, wo + oo, DIMM,
            bo_, y, y, nullptr, DIMM, DIMM, 0);
        ff_fused<<<MROWS / 64, 256, FF_SMEM>>>(y,
            ln2_g + (size_t)L * DIMM, ln2_b + (size_t)L * DIMM,
            w1 + off1, bb1, w2 + off1, bb2, y);
    }

    ln_kernel<<<MROWS / 8, 256>>>(y, (float*)qkv, gf, bf);
    out_transpose_kernel<<<tg, tb>>>((float*)qkv, out);
    (void)in_sizes; (void)n_in; (void)out_size;
}

// round 15
// speedup vs baseline: 1.0324x; 1.0324x over previous
#include <cuda_runtime.h>
#include <cuda_fp16.h>
#include <math.h>
#include <cstdint>

#define DIMM   256
#define TT     8192
#define BB     4
#define HEADSN 8
#define DH     32
#define NB     128
#define BUCKET 64
#define FFD    1024
#define DEPTHN 6
#define MROWS  (BB*TT)
#define BHN    (BB*HEADSN)
#define QKVD   768
#define NBK    (BB*NB)

// ======================= static device scratch =======================
__device__ float g_y  [MROWS*DIMM];
__device__ __half g_qkv[MROWS*QKVD];          // also reused as fp32 final-LN scratch
__device__ __half g_h [MROWS*DIMM];
__device__ __half g_o [MROWS*DIMM];
__device__ __half g_wqkv[DEPTHN*QKVD*DIMM];
__device__ __half g_wo  [DEPTHN*DIMM*DIMM];
__device__ __half g_w1  [DEPTHN*DIMM*FFD];
__device__ __half g_w2  [DEPTHN*FFD*DIMM];
__device__ float g_sq[BHN*NB*DH];
__device__ float g_sk[BHN*NB*DH];
__device__ float g_top[BHN*NB];
__device__ int   g_idx[BHN*NB];

// ======================= helpers =======================
__device__ __forceinline__ uint32_t smem_u32(const void* p) {
    uint32_t a;
    asm("{ .reg .u64 t; cvta.to.shared.u64 t, %1; cvt.u32.u64 %0, t; }" : "=r"(a) : "l"(p));
    return a;
}
__device__ __forceinline__ uint32_t pack_half2(float a, float b) {
    __half2 h = __floats2half2_rn(a, b);
    return *reinterpret_cast<uint32_t*>(&h);
}

#define MMA_F16(c, a, b0, b1) \
    asm volatile("mma.sync.aligned.m16n8k16.row.col.f32.f16.f16.f32 " \
        "{%0,%1,%2,%3}, {%4,%5,%6,%7}, {%8,%9}, {%0,%1,%2,%3};" \
        : "+f"((c)[0]), "+f"((c)[1]), "+f"((c)[2]), "+f"((c)[3]) \
        : "r"((a)[0]), "r"((a)[1]), "r"((a)[2]), "r"((a)[3]), "r"(b0), "r"(b1))

#define LDSM_X4(r, addr) \
    asm volatile("ldmatrix.sync.aligned.m8n8.x4.shared.b16 {%0,%1,%2,%3}, [%4];" \
        : "=r"((r)[0]), "=r"((r)[1]), "=r"((r)[2]), "=r"((r)[3]) : "r"(addr))

#define LDSM_X4_T(r, addr) \
    asm volatile("ldmatrix.sync.aligned.m8n8.x4.trans.shared.b16 {%0,%1,%2,%3}, [%4];" \
        : "=r"((r)[0]), "=r"((r)[1]), "=r"((r)[2]), "=r"((r)[3]) : "r"(addr))

#define CP_ASYNC16(dst, src) \
    asm volatile("cp.async.cg.shared.global [%0], [%1], 16;" :: "r"(dst), "l"(src))
#define CP_COMMIT()  asm volatile("cp.async.commit_group;" ::: "memory")
#define CP_WAIT(n)   asm volatile("cp.async.wait_group %0;" :: "n"(n) : "memory")

// ======================= small kernels =======================
__global__ void pos_add_kernel(const float* __restrict__ x, const float* __restrict__ pe0,
                               const float* __restrict__ pe1, float* __restrict__ y) {
    __shared__ float tile[32][33];
    int b = blockIdx.z, d0 = blockIdx.y * 32, t0 = blockIdx.x * 32;
    int tx = threadIdx.x, ty = threadIdx.y;
    const float* xb = x + (size_t)b * DIMM * TT;
    #pragma unroll
    for (int i = 0; i < 32; i += 8)
        tile[ty + i][tx] = xb[(size_t)(d0 + ty + i) * TT + t0 + tx];
    __syncthreads();
    float* yb = y + (size_t)b * TT * DIMM;
    #pragma unroll
    for (int i = 0; i < 32; i += 8) {
        int t = t0 + ty + i, d = d0 + tx;
        yb[(size_t)t * DIMM + d] =
            tile[tx][ty + i] + pe0[(size_t)(t >> 6) * DIMM + d] + pe1[(size_t)(t & 63) * DIMM + d];
    }
}

__global__ void out_transpose_kernel(const float* __restrict__ hin, float* __restrict__ out) {
    __shared__ float tile[32][33];
    int b = blockIdx.z, d0 = blockIdx.y * 32, t0 = blockIdx.x * 32;
    int tx = threadIdx.x, ty = threadIdx.y;
    const float* hb = hin + (size_t)b * TT * DIMM;
    #pragma unroll
    for (int i = 0; i < 32; i += 8)
        tile[ty + i][tx] = hb[(size_t)(t0 + ty + i) * DIMM + d0 + tx];
    __syncthreads();
    float* ob = out + (size_t)b * DIMM * TT;
    #pragma unroll
    for (int i = 0; i < 32; i += 8)
        ob[(size_t)(d0 + ty + i) * TT + t0 + tx] = tile[tx][ty + i];
}

// LN -> fp32 (final)
__global__ void ln_kernel(const float* __restrict__ in, float* __restrict__ out,
                          const float* __restrict__ g, const float* __restrict__ b) {
    int row = blockIdx.x * 8 + (threadIdx.x >> 5);
    int lane = threadIdx.x & 31;
    const float* r = in + (size_t)row * DIMM;
    float v[8], s = 0.f;
    #pragma unroll
    for (int i = 0; i < 8; i++) { v[i] = r[lane + i * 32]; s += v[i]; }
    #pragma unroll
    for (int off = 16; off; off >>= 1) s += __shfl_xor_sync(0xffffffffu, s, off);
    float m = s * (1.0f / DIMM), var = 0.f;
    #pragma unroll
    for (int i = 0; i < 8; i++) { float d = v[i] - m; var += d * d; }
    #pragma unroll
    for (int off = 16; off; off >>= 1) var += __shfl_xor_sync(0xffffffffu, var, off);
    float inv = rsqrtf(var * (1.0f / DIMM) + 1e-5f);
    float* o = out + (size_t)row * DIMM;
    #pragma unroll
    for (int i = 0; i < 8; i++) {
        int c = lane + i * 32;
        o[c] = (v[i] - m) * inv * g[c] + b[c];
    }
}

// LN -> fp16 only (LN2)
__global__ void ln_h_kernel(const float* __restrict__ in, __half* __restrict__ oh,
                            const float* __restrict__ g, const float* __restrict__ b) {
    int row = blockIdx.x * 8 + (threadIdx.x >> 5);
    int lane = threadIdx.x & 31;
    const float* r = in + (size_t)row * DIMM;
    float v[8], s = 0.f;
    #pragma unroll
    for (int i = 0; i < 8; i++) { v[i] = r[lane + i * 32]; s += v[i]; }
    #pragma unroll
    for (int off = 16; off; off >>= 1) s += __shfl_xor_sync(0xffffffffu, s, off);
    float m = s * (1.0f / DIMM), var = 0.f;
    #pragma unroll
    for (int i = 0; i < 8; i++) { float d = v[i] - m; var += d * d; }
    #pragma unroll
    for (int off = 16; off; off >>= 1) var += __shfl_xor_sync(0xffffffffu, var, off);
    float inv = rsqrtf(var * (1.0f / DIMM) + 1e-5f);
    #pragma unroll
    for (int i = 0; i < 8; i++) {
        int c = lane + i * 32;
        oh[(size_t)row * DIMM + c] = __float2half((v[i] - m) * inv * g[c] + b[c]);
    }
}

// LN1 + routing projections fused: y -> h fp16, bucket mean in smem, sq/sk = hm @ Wq/Wkv
__global__ void ln1_route_kernel(const float* __restrict__ y, __half* __restrict__ oh,
                                 const float* __restrict__ g, const float* __restrict__ b,
                                 const float* __restrict__ Wq, const float* __restrict__ Wkv) {
    __shared__ float acc[8][DIMM];
    __shared__ float hm[DIMM];
    int bu = blockIdx.x;
    int warp = threadIdx.x >> 5, lane = threadIdx.x & 31;
    float la[8];
    #pragma unroll
    for (int i = 0; i < 8; i++) la[i] = 0.f;
    for (int rr = 0; rr < 8; rr++) {
        int row = bu * BUCKET + warp * 8 + rr;
        const float* r = y + (size_t)row * DIMM;
        float v[8], s = 0.f;
        #pragma unroll
        for (int i = 0; i < 8; i++) { v[i] = r[lane + i * 32]; s += v[i]; }
        #pragma unroll
        for (int off = 16; off; off >>= 1) s += __shfl_xor_sync(0xffffffffu, s, off);
        float m = s * (1.0f / DIMM), var = 0.f;
        #pragma unroll
        for (int i = 0; i < 8; i++) { float d = v[i] - m; var += d * d; }
        #pragma unroll
        for (int off = 16; off; off >>= 1) var += __shfl_xor_sync(0xffffffffu, var, off);
        float inv = rsqrtf(var * (1.0f / DIMM) + 1e-5f);
        #pragma unroll
        for (int i = 0; i < 8; i++) {
            int c = lane + i * 32;
            float val = (v[i] - m) * inv * g[c] + b[c];
            oh[(size_t)row * DIMM + c] = __float2half(val);
            la[i] += val;
        }
    }
    #pragma unroll
    for (int i = 0; i < 8; i++) acc[warp][lane + i * 32] = la[i];
    __syncthreads();
    for (int c = threadIdx.x; c < DIMM; c += 256) {
        float s = 0.f;
        #pragma unroll
        for (int w = 0; w < 8; w++) s += acc[w][c];
        hm[c] = s * (1.0f / BUCKET);
    }
    __syncthreads();
    // routing projections (fp32-exact): sq = hm @ Wq[:, c], sk = hm @ Wkv[:, c]
    int bb2 = bu >> 7, u = bu & 127;
    int c = threadIdx.x;
    int h = c >> 5, e = c & 31;
    size_t dst = (((size_t)(bb2 * HEADSN + h)) * NB + u) * DH + e;
    {
        float a = 0.f;
        #pragma unroll 8
        for (int k = 0; k < DIMM; k++) a = fmaf(hm[k], Wq[(size_t)k * DIMM + c], a);
        g_sq[dst] = a;
    }
    {
        float a = 0.f;
        #pragma unroll 8
        for (int k = 0; k < DIMM; k++) a = fmaf(hm[k], Wkv[(size_t)k * (2 * DIMM) + c], a);
        g_sk[dst] = a;
    }
}

__global__ void wconv_kernel(const float* __restrict__ W, __half* __restrict__ T,
                             int K, int N, size_t lstride) {
    __shared__ float t[32][33];
    int l = blockIdx.z;
    const float* Wl = W + (size_t)l * K * N;
    size_t ob = (size_t)l * lstride;
    int n0 = blockIdx.x * 32, k0 = blockIdx.y * 32;
    int tx = threadIdx.x, ty = threadIdx.y;
    #pragma unroll
    for (int i = 0; i < 32; i += 8)
        t[ty + i][tx] = Wl[(size_t)(k0 + ty + i) * N + n0 + tx];
    __syncthreads();
    #pragma unroll
    for (int i = 0; i < 32; i += 8)
        T[ob + (size_t)(n0 + ty + i) * K + k0 + tx] = __float2half(t[tx][ty + i]);
}

// ======================= pipelined fp16 HMMA GEMM (128x128) =======================
#define AH_OFF 0
#define BH_OFF 16384
#define STAGE_SZ 32768
#define NSTAGE 3
#define GEMM_SMEM (NSTAGE*STAGE_SZ)

__device__ __forceinline__ void gemm_load_stage(
    uint32_t sb, int stg, int tid, int k0,
    const __half* __restrict__ Ah, int lda,
    const __half* __restrict__ Bh, int ldb,
    int m0, int n0) {
    uint32_t base = sb + stg * STAGE_SZ;
    #pragma unroll
    for (int p = 0; p < 4; ++p) {
        int lin = p * 256 + tid;
        int r = lin >> 3, kb = lin & 7;
        uint32_t soff = (uint32_t)(r * 128 + ((kb ^ (r & 7)) << 4));
        CP_ASYNC16(base + AH_OFF + soff, Ah + (size_t)(m0 + r) * lda + k0 + kb * 8);
        CP_ASYNC16(base + BH_OFF + soff, Bh + (size_t)(n0 + r) * ldb + k0 + kb * 8);
    }
}

__global__ __launch_bounds__(256)
void hmma_gemm(const __half* __restrict__ Ah, int lda,
               const __half* __restrict__ Bh, int ldb,
               const float* __restrict__ bias, const float* __restrict__ resid,
               float* __restrict__ Cf, __half* __restrict__ Ch,
               int ldc, int K, int gelu) {
    extern __shared__ char smem[];
    uint32_t sb = smem_u32(smem);
    int tid = threadIdx.x;
    int lane = tid & 31, wid = tid >> 5;
    int wm = wid >> 2, wn = wid & 3;
    int m0 = blockIdx.y * 128, n0 = blockIdx.x * 128;

    float acc[4][4][4];
    #pragma unroll
    for (int i = 0; i < 4; i++)
        #pragma unroll
        for (int j = 0; j < 4; j++)
            #pragma unroll
            for (int k = 0; k < 4; k++) acc[i][j][k] = 0.f;

    int a_row = (lane & 15);
    int a_kh  = (lane >> 4);
    int b_sub = (lane >> 3);
    int b_row = ((b_sub >> 1) << 3) + (lane & 7);
    int b_kh  = (b_sub & 1);

    const int nch = K >> 6;
    gemm_load_stage(sb, 0, tid, 0, Ah, lda, Bh, ldb, m0, n0);
    CP_COMMIT();
    if (nch > 1) {
        gemm_load_stage(sb, 1, tid, 64, Ah, lda, Bh, ldb, m0, n0);
        CP_COMMIT();
    }

    for (int ch = 0; ch < nch; ++ch) {
        if (ch + 2 < nch) {
            gemm_load_stage(sb, (ch + 2) % NSTAGE, tid, (ch + 2) << 6, Ah, lda, Bh, ldb, m0, n0);
            CP_COMMIT();
            CP_WAIT(2);
        } else if (ch + 1 < nch) {
            CP_WAIT(1);
        } else {
            CP_WAIT(0);
        }
        __syncthreads();

        uint32_t stg = sb + (ch % NSTAGE) * STAGE_SZ;
        #pragma unroll
        for (int ks = 0; ks < 4; ++ks) {
            uint32_t bhf[4][2];
            #pragma unroll
            for (int pair = 0; pair < 2; ++pair) {
                int row = wn * 32 + pair * 16 + b_row;
                int kb = ks * 2 + b_kh;
                uint32_t addr = stg + (uint32_t)(row * 128 + ((kb ^ (row & 7)) << 4));
                uint32_t rg[4];
                LDSM_X4(rg, addr + BH_OFF);
                bhf[pair * 2][0] = rg[0]; bhf[pair * 2][1] = rg[1];
                bhf[pair * 2 + 1][0] = rg[2]; bhf[pair * 2 + 1][1] = rg[3];
            }
            #pragma unroll
            for (int mt = 0; mt < 4; ++mt) {
                int row = wm * 64 + mt * 16 + a_row;
                int kb = ks * 2 + a_kh;
                uint32_t addr = stg + (uint32_t)(row * 128 + ((kb ^ (row & 7)) << 4));
                uint32_t ah[4];
                LDSM_X4(ah, addr + AH_OFF);
                #pragma unroll
                for (int nt = 0; nt < 4; ++nt)
                    MMA_F16(acc[mt][nt], ah, bhf[nt][0], bhf[nt][1]);
            }
        }
        __syncthreads();
    }

    int rbase = m0 + wm * 64 + (lane >> 2);
    int cbase = n0 + wn * 32 + (lane & 3) * 2;
    #pragma unroll
    for (int mt = 0; mt < 4; ++mt) {
        #pragma unroll
        for (int nt = 0; nt < 4; ++nt) {
            #pragma unroll
            for (int half = 0; half < 2; ++half) {
                int gm = rbase + mt * 16 + half * 8;
                int gn = cbase + nt * 8;
                float v0 = acc[mt][nt][half * 2 + 0];
                float v1 = acc[mt][nt][half * 2 + 1];
                if (bias) { v0 += bias[gn]; v1 += bias[gn + 1]; }
                if (gelu) {
                    v0 = 0.5f * v0 * (1.0f + erff(v0 * 0.70710678118654752f));
                    v1 = 0.5f * v1 * (1.0f + erff(v1 * 0.70710678118654752f));
                }
                size_t go = (size_t)gm * ldc + gn;
                if (resid) { v0 += resid[go]; v1 += resid[go + 1]; }
                if (Cf) {
                    *reinterpret_cast<float2*>(Cf + go) = make_float2(v0, v1);
                } else {
                    *reinterpret_cast<__half2*>(Ch + go) = __floats2half2_rn(v0, v1);
                }
            }
        }
    }
}

// ======================= fused MLP: y += gelu(h@W1+b1)@W2 + b2 =======================
#define FH_OFF  0
#define FP_OFF  32768
#define FW1_OFF 40960
#define FW2_OFF 106496
#define FF_SMEM 172032

__device__ __forceinline__ void ff_load_w(uint32_t sb, int buf, int tid, int c,
                                          const __half* __restrict__ W1T,
                                          const __half* __restrict__ W2T) {
    #pragma unroll
    for (int p = 0; p < 8; ++p) {
        int lin = p * 256 + tid;
        int r = lin >> 5;
        int rest = lin & 31;
        int pl = rest >> 3, kb = rest & 7;
        uint32_t dst = sb + FW1_OFF + buf * 32768 +
                       (uint32_t)(pl * 8192 + r * 128 + ((kb ^ (r & 7)) << 4));
        CP_ASYNC16(dst, W1T + (size_t)(c * 64 + r) * DIMM + pl * 64 + kb * 8);
    }
    #pragma unroll
    for (int p = 0; p < 8; ++p) {
        int lin = p * 256 + tid;
        int r = lin >> 3, kb = lin & 7;
        uint32_t dst = sb + FW2_OFF + buf * 32768 +
                       (uint32_t)(r * 128 + ((kb ^ (r & 7)) << 4));
        CP_ASYNC16(dst, W2T + (size_t)r * FFD + c * 64 + kb * 8);
    }
}

__global__ __launch_bounds__(256)
void ff_fused(const __half* __restrict__ h,
              const __half* __restrict__ W1T, const float* __restrict__ b1,
              const __half* __restrict__ W2T, const float* __restrict__ b2,
              float* __restrict__ y) {
    extern __shared__ char smem[];
    uint32_t sb = smem_u32(smem);
    int tid = threadIdx.x;
    int lane = tid & 31, wid = tid >> 5;
    int wm = wid >> 2, wn = wid & 3;      // 2 x 4
    int m0 = blockIdx.x * 64;

    int a_row = (lane & 15);
    int a_kh  = (lane >> 4);
    int b_sub = (lane >> 3);
    int b_row = ((b_sub >> 1) << 3) + (lane & 7);
    int b_kh  = (b_sub & 1);

    float acc_out[2][8][4];
    #pragma unroll
    for (int i = 0; i < 2; i++)
        #pragma unroll
        for (int j = 0; j < 8; j++)
            #pragma unroll
            for (int k = 0; k < 4; k++) acc_out[i][j][k] = 0.f;

    // load h tile (64 x 256) into 4 k-planes, once; group 0 also carries W(0)
    #pragma unroll
    for (int p = 0; p < 8; ++p) {
        int lin = p * 256 + tid;
        int r = lin >> 5;
        int rest = lin & 31;
        int pl = rest >> 3, kb = rest & 7;
        uint32_t dst = sb + FH_OFF + (uint32_t)(pl * 8192 + r * 128 + ((kb ^ (r & 7)) << 4));
        CP_ASYNC16(dst, h + (size_t)(m0 + r) * DIMM + pl * 64 + kb * 8);
    }
    ff_load_w(sb, 0, tid, 0, W1T, W2T);
    CP_COMMIT();
    ff_load_w(sb, 1, tid, 1, W1T, W2T);
    CP_COMMIT();

    for (int c = 0; c < 16; ++c) {
        int buf = c & 1;
        if (c < 15) CP_WAIT(1);
        else        CP_WAIT(0);
        __syncthreads();

        // ---- gemm1: P_raw(64x64) = h(64x256) @ W1chunk^T ----
        float acc1[2][2][4];
        #pragma unroll
        for (int i = 0; i < 2; i++)
            #pragma unroll
            for (int j = 0; j < 2; j++)
                #pragma unroll
                for (int k = 0; k < 4; k++) acc1[i][j][k] = 0.f;
        uint32_t w1b = sb + FW1_OFF + buf * 32768;
        #pragma unroll
        for (int ks = 0; ks < 16; ++ks) {
            int pl = ks >> 2, k2 = ks & 3;
            uint32_t rgB[4];
            {
                int row = wn * 16 + b_row;
                int kb = k2 * 2 + b_kh;
                LDSM_X4(rgB, w1b + (uint32_t)(pl * 8192 + row * 128 + ((kb ^ (row & 7)) << 4)));
            }
            #pragma unroll
            for (int mt = 0; mt < 2; ++mt) {
                int row = wm * 32 + mt * 16 + a_row;
                int kb = k2 * 2 + a_kh;
                uint32_t ah[4];
                LDSM_X4(ah, sb + FH_OFF + (uint32_t)(pl * 8192 + row * 128 + ((kb ^ (row & 7)) << 4)));
                MMA_F16(acc1[mt][0], ah, rgB[0], rgB[1]);
                MMA_F16(acc1[mt][1], ah, rgB[2], rgB[3]);
            }
        }

        // ---- bias1 + gelu, store P ----
        #pragma unroll
        for (int mt = 0; mt < 2; ++mt) {
            #pragma unroll
            for (int nt = 0; nt < 2; ++nt) {
                #pragma unroll
                for (int half = 0; half < 2; ++half) {
                    int pr = wm * 32 + mt * 16 + half * 8 + (lane >> 2);
                    int pc = wn * 16 + nt * 8 + (lane & 3) * 2;
                    float v0 = acc1[mt][nt][half * 2 + 0] + b1[c * 64 + pc];
                    float v1 = acc1[mt][nt][half * 2 + 1] + b1[c * 64 + pc + 1];
                    v0 = 0.5f * v0 * (1.0f + erff(v0 * 0.70710678118654752f));
                    v1 = 0.5f * v1 * (1.0f + erff(v1 * 0.70710678118654752f));
                    uint32_t addr = sb + FP_OFF +
                        (uint32_t)(pr * 128 + (((pc >> 3) ^ (pr & 7)) << 4) + (pc & 7) * 2);
                    asm volatile("st.shared.b32 [%0], %1;" :: "r"(addr), "r"(pack_half2(v0, v1)));
                }
            }
        }
        __syncthreads();

        // ---- gemm2: acc_out += P(64x64) @ W2chunk^T ----
        uint32_t w2b = sb + FW2_OFF + buf * 32768;
        #pragma unroll
        for (int ks = 0; ks < 4; ++ks) {
            uint32_t bfr[8][2];
            #pragma unroll
            for (int pair = 0; pair < 4; ++pair) {
                int row = wn * 64 + pair * 16 + b_row;
                int kb = ks * 2 + b_kh;
                uint32_t rg[4];
                LDSM_X4(rg, w2b + (uint32_t)(row * 128 + ((kb ^ (row & 7)) << 4)));
                bfr[pair * 2][0] = rg[0]; bfr[pair * 2][1] = rg[1];
                bfr[pair * 2 + 1][0] = rg[2]; bfr[pair * 2 + 1][1] = rg[3];
            }
            #pragma unroll
            for (int mt = 0; mt < 2; ++mt) {
                int row = wm * 32 + mt * 16 + a_row;
                int kb = ks * 2 + a_kh;
                uint32_t ah[4];
                LDSM_X4(ah, sb + FP_OFF + (uint32_t)(row * 128 + ((kb ^ (row & 7)) << 4)));
                #pragma unroll
                for (int nt = 0; nt < 8; ++nt)
                    MMA_F16(acc_out[mt][nt], ah, bfr[nt][0], bfr[nt][1]);
            }
        }
        __syncthreads();

        if (c + 2 < 16) {
            ff_load_w(sb, buf, tid, c + 2, W1T, W2T);
            CP_COMMIT();
        }
    }

    // ---- epilogue: + bias2 + residual y -> y ----
    int rbase = m0 + wm * 32 + (lane >> 2);
    int cbase = wn * 64 + (lane & 3) * 2;
    #pragma unroll
    for (int mt = 0; mt < 2; ++mt) {
        #pragma unroll
        for (int nt = 0; nt < 8; ++nt) {
            #pragma unroll
            for (int half = 0; half < 2; ++half) {
                int gm = rbase + mt * 16 + half * 8;
                int gn = cbase + nt * 8;
                size_t go = (size_t)gm * DIMM + gn;
                float v0 = acc_out[mt][nt][half * 2 + 0] + b2[gn]     + y[go];
                float v1 = acc_out[mt][nt][half * 2 + 1] + b2[gn + 1] + y[go + 1];
                *reinterpret_cast<float2*>(y + go) = make_float2(v0, v1);
            }
        }
    }
}

// ======================= attention =======================
__global__ void routing_kernel() {
    int bh = blockIdx.x;
    int i = threadIdx.x;
    __shared__ float ssk[NB][DH];
    const float* base = g_sk + (size_t)bh * NB * DH;
    for (int idx = i; idx < NB * DH; idx += NB) ssk[idx / DH][idx % DH] = base[idx];
    float sq[DH];
    const float* sqp = g_sq + ((size_t)bh * NB + i) * DH;
    #pragma unroll
    for (int e = 0; e < DH; e++) sq[e] = sqp[e];
    __syncthreads();
    const float sc = 0.17677669529663687f * (1.0f / 0.75f);
    float mx = -1e30f; int am = 0;
    for (int j = 0; j < NB; j++) {
        float d = 0.f;
        #pragma unroll
        for (int e = 0; e < DH; e++) d = fmaf(sq[e], ssk[j][e], d);
        d *= sc;
        if (d > mx) { mx = d; am = j; }
    }
    float sum = 0.f;
    for (int j = 0; j < NB; j++) {
        float d = 0.f;
        #pragma unroll
        for (int e = 0; e < DH; e++) d = fmaf(sq[e], ssk[j][e], d);
        sum += expf(d * sc - mx);
    }
    g_top[bh * NB + i] = 1.0f / sum;
    g_idx[bh * NB + i] = am;
}

__global__ __launch_bounds__(128)
void attn_kernel(const __half* __restrict__ qkv, __half* __restrict__ o) {
    __shared__ __half sQ[64 * 40];
    __shared__ __half sK[128 * 40];
    __shared__ __half sV[128 * 40];
    int u = blockIdx.x, bh = blockIdx.y;
    int b = bh >> 3, h = bh & 7;
    int tid = threadIdx.x, lane = tid & 31, warp = tid >> 5;
    float top = g_top[bh * NB + u];
    int ridx = g_idx[bh * NB + u];
    const __half* qg = qkv + ((size_t)(b * TT + u * BUCKET)) * QKVD + h * DH;
    const __half* kgs = qg + 256;
    const __half* kgr = qkv + ((size_t)(b * TT + ridx * BUCKET)) * QKVD + 256 + h * DH;
    uint32_t sqa = smem_u32(sQ), ska = smem_u32(sK), sva = smem_u32(sV);

    #pragma unroll
    for (int i = tid; i < 256; i += 128) {
        int r = i >> 2, cb = i & 3;
        CP_ASYNC16(sqa + r * 80 + cb * 16, qg + (size_t)r * QKVD + cb * 8);
    }
    #pragma unroll
    for (int i = tid; i < 512; i += 128) {
        int r = i >> 2, cb = i & 3;
        const __half* kr = (r < 64) ? kgr + (size_t)r * QKVD : kgs + (size_t)(r - 64) * QKVD;
        CP_ASYNC16(ska + r * 80 + cb * 16, kr + cb * 8);
        CP_ASYNC16(sva + r * 80 + cb * 16, kr + 256 + cb * 8);
    }
    CP_COMMIT(); CP_WAIT(0);
    __syncthreads();

    uint32_t qa[2][4];
    #pragma unroll
    for (int kh = 0; kh < 2; ++kh) {
        uint32_t addr = sqa + (uint32_t)((warp * 16 + (lane & 15)) * 80 + (lane >> 4) * 16 + kh * 32);
        LDSM_X4(qa[kh], addr);
    }

    float acc[16][4];
    #pragma unroll
    for (int t = 0; t < 16; t++)
        #pragma unroll
        for (int j = 0; j < 4; j++) acc[t][j] = 0.f;
    int b_sub = lane >> 3;
    int b_row = ((b_sub >> 1) << 3) + (lane & 7);
    int b_kh  = b_sub & 1;
    #pragma unroll
    for (int pair = 0; pair < 8; ++pair) {
        #pragma unroll
        for (int kh = 0; kh < 2; ++kh) {
            uint32_t addr = ska + (uint32_t)((pair * 16 + b_row) * 80 + kh * 32 + b_kh * 16);
            uint32_t rg[4];
            LDSM_X4(rg, addr);
            MMA_F16(acc[pair * 2],     qa[kh], rg[0], rg[1]);
            MMA_F16(acc[pair * 2 + 1], qa[kh], rg[2], rg[3]);
        }
    }

    const float scale = 0.17677669529663687f;
    #pragma unroll
    for (int t = 0; t < 16; t++) {
        float f = (t < 8) ? scale * top : scale;
        #pragma unroll
        for (int j = 0; j < 4; j++) acc[t][j] *= f;
    }
    float mx0 = -1e30f, mx1 = -1e30f;
    #pragma unroll
    for (int t = 0; t < 16; t++) {
        mx0 = fmaxf(mx0, fmaxf(acc[t][0], acc[t][1]));
        mx1 = fmaxf(mx1, fmaxf(acc[t][2], acc[t][3]));
    }
    #pragma unroll
    for (int off = 1; off < 4; off <<= 1) {
        mx0 = fmaxf(mx0, __shfl_xor_sync(0xffffffffu, mx0, off));
        mx1 = fmaxf(mx1, __shfl_xor_sync(0xffffffffu, mx1, off));
    }
    float s0 = 0.f, s1 = 0.f;
    #pragma unroll
    for (int t = 0; t < 16; t++) {
        acc[t][0] = __expf(acc[t][0] - mx0);
        acc[t][1] = __expf(acc[t][1] - mx0);
        acc[t][2] = __expf(acc[t][2] - mx1);
        acc[t][3] = __expf(acc[t][3] - mx1);
        s0 += acc[t][0] + acc[t][1];
        s1 += acc[t][2] + acc[t][3];
    }
    #pragma unroll
    for (int off = 1; off < 4; off <<= 1) {
        s0 += __shfl_xor_sync(0xffffffffu, s0, off);
        s1 += __shfl_xor_sync(0xffffffffu, s1, off);
    }
    float i0 = 1.0f / s0, i1 = 1.0f / s1;
    #pragma unroll
    for (int t = 0; t < 16; t++) {
        float f0 = (t < 8) ? i0 * top : i0;
        float f1 = (t < 8) ? i1 * top : i1;
        acc[t][0] *= f0; acc[t][1] *= f0;
        acc[t][2] *= f1; acc[t][3] *= f1;
    }

    float out[4][4];
    #pragma unroll
    for (int nt = 0; nt < 4; nt++)
        #pragma unroll
        for (int j = 0; j < 4; j++) out[nt][j] = 0.f;
    int v_row = (lane & 7) + ((lane >> 3) & 1) * 8;
    int v_ch  = (lane >> 4);
    #pragma unroll
    for (int s = 0; s < 8; ++s) {
        uint32_t pa[4];
        pa[0] = pack_half2(acc[2*s][0],   acc[2*s][1]);
        pa[1] = pack_half2(acc[2*s][2],   acc[2*s][3]);
        pa[2] = pack_half2(acc[2*s+1][0], acc[2*s+1][1]);
        pa[3] = pack_half2(acc[2*s+1][2], acc[2*s+1][3]);
        #pragma unroll
        for (int nh = 0; nh < 2; ++nh) {
            uint32_t addr = sva + (uint32_t)((s * 16 + v_row) * 80 + nh * 32 + v_ch * 16);
            uint32_t rg[4];
            LDSM_X4_T(rg, addr);
            MMA_F16(out[nh * 2],     pa, rg[0], rg[1]);
            MMA_F16(out[nh * 2 + 1], pa, rg[2], rg[3]);
        }
    }

    int r0 = warp * 16 + (lane >> 2);
    size_t ob = ((size_t)(b * TT + u * BUCKET + r0)) * DIMM + h * DH;
    #pragma unroll
    for (int nt = 0; nt < 4; ++nt) {
        int col = nt * 8 + (lane & 3) * 2;
        *reinterpret_cast<__half2*>(o + ob + col) = __floats2half2_rn(out[nt][0], out[nt][1]);
        *reinterpret_cast<__half2*>(o + ob + 8 * DIMM + col) = __floats2half2_rn(out[nt][2], out[nt][3]);
    }
}

// ======================= host orchestration =======================
extern "C" void kernel_launch(void* const* d_in, const int* in_sizes, int n_in,
                              void* d_out, int out_size) {
    const float* x     = (const float*)d_in[0];
    const float* pe0   = (const float*)d_in[1];
    const float* pe1   = (const float*)d_in[2];
    const float* ln1_g = (const float*)d_in[3];
    const float* ln1_b = (const float*)d_in[4];
    const float* Wq    = (const float*)d_in[5];
    const float* Wkv   = (const float*)d_in[6];
    const float* Wo    = (const float*)d_in[7];
    const float* bo    = (const float*)d_in[8];
    const float* ln2_g = (const float*)d_in[9];
    const float* ln2_b = (const float*)d_in[10];
    const float* W1    = (const float*)d_in[11];
    const float* b1    = (const float*)d_in[12];
    const float* W2    = (const float*)d_in[13];
    const float* b2    = (const float*)d_in[14];
    const float* gf    = (const float*)d_in[15];
    const float* bf    = (const float*)d_in[16];
    float* out = (float*)d_out;

    cudaFuncSetAttribute(hmma_gemm, cudaFuncAttributeMaxDynamicSharedMemorySize, GEMM_SMEM);
    cudaFuncSetAttribute(ff_fused,  cudaFuncAttributeMaxDynamicSharedMemorySize, FF_SMEM);

    float *y;
    __half *qkv, *h, *o;
    __half *wqkv, *wo, *w1, *w2;
    cudaGetSymbolAddress((void**)&y, g_y);
    cudaGetSymbolAddress((void**)&qkv, g_qkv);
    cudaGetSymbolAddress((void**)&h, g_h);
    cudaGetSymbolAddress((void**)&o, g_o);
    cudaGetSymbolAddress((void**)&wqkv, g_wqkv);
    cudaGetSymbolAddress((void**)&wo, g_wo);
    cudaGetSymbolAddress((void**)&w1, g_w1);
    cudaGetSymbolAddress((void**)&w2, g_w2);

    dim3 tb(32, 8);
    const size_t QKV_LS = (size_t)QKVD * DIMM;
    wconv_kernel<<<dim3(DIMM / 32,   DIMM / 32, DEPTHN), tb>>>(Wq,  wqkv, DIMM, DIMM, QKV_LS);
    wconv_kernel<<<dim3(2*DIMM / 32, DIMM / 32, DEPTHN), tb>>>(Wkv, wqkv + 256 * DIMM, DIMM, 2*DIMM, QKV_LS);
    wconv_kernel<<<dim3(DIMM / 32,   DIMM / 32, DEPTHN), tb>>>(Wo,  wo, DIMM, DIMM, (size_t)DIMM * DIMM);
    wconv_kernel<<<dim3(FFD / 32,    DIMM / 32, DEPTHN), tb>>>(W1,  w1, DIMM, FFD, (size_t)DIMM * FFD);
    wconv_kernel<<<dim3(DIMM / 32,   FFD / 32,  DEPTHN), tb>>>(W2,  w2, FFD,  DIMM, (size_t)DIMM * FFD);

    dim3 tg(TT / 32, DIMM / 32, BB);
    pos_add_kernel<<<tg, tb>>>(x, pe0, pe1, y);

    for (int L = 0; L < DEPTHN; L++) {
        const float* g1 = ln1_g + (size_t)L * DIMM;
        const float* bb = ln1_b + (size_t)L * DIMM;
        const float* bo_ = bo + (size_t)L * DIMM;
        const float* bb1 = b1 + (size_t)L * FFD;
        const float* bb2 = b2 + (size_t)L * DIMM;
        size_t oqkv = (size_t)L * QKV_LS;
        size_t oo   = (size_t)L * DIMM * DIMM;
        size_t off1 = (size_t)L * DIMM * FFD;

        ln1_route_kernel<<<NBK, 256>>>(y, h, g1, bb,
            Wq + (size_t)L * DIMM * DIMM, Wkv + (size_t)L * DIMM * 2 * DIMM);
        routing_kernel<<<BHN, NB>>>();
        hmma_gemm<<<dim3(QKVD / 128, MROWS / 128), 256, GEMM_SMEM>>>(h, DIMM,
            wqkv + oqkv, DIMM, nullptr, nullptr, nullptr, qkv, QKVD, DIMM, 0);
        attn_kernel<<<dim3(NB, BHN), 128>>>(qkv, o);
        hmma_gemm<<<dim3(2, MROWS / 128), 256, GEMM_SMEM>>>(o, DIMM, wo + oo, DIMM,
            bo_, y, y, nullptr, DIMM, DIMM, 0);
        ln_h_kernel<<<MROWS / 8, 256>>>(y, h, ln2_g + (size_t)L * DIMM, ln2_b + (size_t)L * DIMM);
        ff_fused<<<MROWS / 64, 256, FF_SMEM>>>(h, w1 + off1, bb1, w2 + off1, bb2, y);
    }

    ln_kernel<<<MROWS / 8, 256>>>(y, (float*)qkv, gf, bf);
    out_transpose_kernel<<<tg, tb>>>((float*)qkv, out);
    (void)in_sizes; (void)n_in; (void)out_size;
}

// round 16
// speedup vs baseline: 1.1334x; 1.0979x over previous
#include <cuda_runtime.h>
#include <cuda_fp16.h>
#include <math.h>
#include <cstdint>

#define DIMM   256
#define TT     8192
#define BB     4
#define HEADSN 8
#define DH     32
#define NB     128
#define BUCKET 64
#define FFD    1024
#define DEPTHN 6
#define MROWS  (BB*TT)
#define BHN    (BB*HEADSN)
#define QKVD   768
#define NBK    (BB*NB)

// ======================= static device scratch =======================
__device__ float g_y  [MROWS*DIMM];
__device__ __half g_qkv[MROWS*QKVD];          // also reused as fp32 final-LN scratch
__device__ __half g_h [MROWS*DIMM];
__device__ __half g_o [MROWS*DIMM];
__device__ __half g_wqkv[DEPTHN*QKVD*DIMM];
__device__ __half g_wo  [DEPTHN*DIMM*DIMM];
__device__ __half g_w1  [DEPTHN*DIMM*FFD];
__device__ __half g_w2  [DEPTHN*FFD*DIMM];
__device__ float g_sq[BHN*NB*DH];
__device__ float g_sk[BHN*NB*DH];
__device__ float g_top[BHN*NB];
__device__ int   g_idx[BHN*NB];

// ======================= helpers =======================
__device__ __forceinline__ uint32_t smem_u32(const void* p) {
    uint32_t a;
    asm("{ .reg .u64 t; cvta.to.shared.u64 t, %1; cvt.u32.u64 %0, t; }" : "=r"(a) : "l"(p));
    return a;
}
__device__ __forceinline__ uint32_t pack_half2(float a, float b) {
    __half2 h = __floats2half2_rn(a, b);
    return *reinterpret_cast<uint32_t*>(&h);
}

#define MMA_F16(c, a, b0, b1) \
    asm volatile("mma.sync.aligned.m16n8k16.row.col.f32.f16.f16.f32 " \
        "{%0,%1,%2,%3}, {%4,%5,%6,%7}, {%8,%9}, {%0,%1,%2,%3};" \
        : "+f"((c)[0]), "+f"((c)[1]), "+f"((c)[2]), "+f"((c)[3]) \
        : "r"((a)[0]), "r"((a)[1]), "r"((a)[2]), "r"((a)[3]), "r"(b0), "r"(b1))

#define LDSM_X4(r, addr) \
    asm volatile("ldmatrix.sync.aligned.m8n8.x4.shared.b16 {%0,%1,%2,%3}, [%4];" \
        : "=r"((r)[0]), "=r"((r)[1]), "=r"((r)[2]), "=r"((r)[3]) : "r"(addr))

#define LDSM_X4_T(r, addr) \
    asm volatile("ldmatrix.sync.aligned.m8n8.x4.trans.shared.b16 {%0,%1,%2,%3}, [%4];" \
        : "=r"((r)[0]), "=r"((r)[1]), "=r"((r)[2]), "=r"((r)[3]) : "r"(addr))

#define CP_ASYNC16(dst, src) \
    asm volatile("cp.async.cg.shared.global [%0], [%1], 16;" :: "r"(dst), "l"(src))
#define CP_COMMIT()  asm volatile("cp.async.commit_group;" ::: "memory")
#define CP_WAIT(n)   asm volatile("cp.async.wait_group %0;" :: "n"(n) : "memory")

// ======================= small kernels =======================
__global__ void pos_add_kernel(const float* __restrict__ x, const float* __restrict__ pe0,
                               const float* __restrict__ pe1, float* __restrict__ y) {
    __shared__ float tile[32][33];
    int b = blockIdx.z, d0 = blockIdx.y * 32, t0 = blockIdx.x * 32;
    int tx = threadIdx.x, ty = threadIdx.y;
    const float* xb = x + (size_t)b * DIMM * TT;
    #pragma unroll
    for (int i = 0; i < 32; i += 8)
        tile[ty + i][tx] = xb[(size_t)(d0 + ty + i) * TT + t0 + tx];
    __syncthreads();
    float* yb = y + (size_t)b * TT * DIMM;
    #pragma unroll
    for (int i = 0; i < 32; i += 8) {
        int t = t0 + ty + i, d = d0 + tx;
        yb[(size_t)t * DIMM + d] =
            tile[tx][ty + i] + pe0[(size_t)(t >> 6) * DIMM + d] + pe1[(size_t)(t & 63) * DIMM + d];
    }
}

__global__ void out_transpose_kernel(const float* __restrict__ hin, float* __restrict__ out) {
    __shared__ float tile[32][33];
    int b = blockIdx.z, d0 = blockIdx.y * 32, t0 = blockIdx.x * 32;
    int tx = threadIdx.x, ty = threadIdx.y;
    const float* hb = hin + (size_t)b * TT * DIMM;
    #pragma unroll
    for (int i = 0; i < 32; i += 8)
        tile[ty + i][tx] = hb[(size_t)(t0 + ty + i) * DIMM + d0 + tx];
    __syncthreads();
    float* ob = out + (size_t)b * DIMM * TT;
    #pragma unroll
    for (int i = 0; i < 32; i += 8)
        ob[(size_t)(d0 + ty + i) * TT + t0 + tx] = tile[tx][ty + i];
}

// LN -> fp32 (final)
__global__ void ln_kernel(const float* __restrict__ in, float* __restrict__ out,
                          const float* __restrict__ g, const float* __restrict__ b) {
    int row = blockIdx.x * 8 + (threadIdx.x >> 5);
    int lane = threadIdx.x & 31;
    const float* r = in + (size_t)row * DIMM;
    float v[8], s = 0.f;
    #pragma unroll
    for (int i = 0; i < 8; i++) { v[i] = r[lane + i * 32]; s += v[i]; }
    #pragma unroll
    for (int off = 16; off; off >>= 1) s += __shfl_xor_sync(0xffffffffu, s, off);
    float m = s * (1.0f / DIMM), var = 0.f;
    #pragma unroll
    for (int i = 0; i < 8; i++) { float d = v[i] - m; var += d * d; }
    #pragma unroll
    for (int off = 16; off; off >>= 1) var += __shfl_xor_sync(0xffffffffu, var, off);
    float inv = rsqrtf(var * (1.0f / DIMM) + 1e-5f);
    float* o = out + (size_t)row * DIMM;
    #pragma unroll
    for (int i = 0; i < 8; i++) {
        int c = lane + i * 32;
        o[c] = (v[i] - m) * inv * g[c] + b[c];
    }
}

// LN -> fp16 only (LN2)
__global__ void ln_h_kernel(const float* __restrict__ in, __half* __restrict__ oh,
                            const float* __restrict__ g, const float* __restrict__ b) {
    int row = blockIdx.x * 8 + (threadIdx.x >> 5);
    int lane = threadIdx.x & 31;
    const float* r = in + (size_t)row * DIMM;
    float v[8], s = 0.f;
    #pragma unroll
    for (int i = 0; i < 8; i++) { v[i] = r[lane + i * 32]; s += v[i]; }
    #pragma unroll
    for (int off = 16; off; off >>= 1) s += __shfl_xor_sync(0xffffffffu, s, off);
    float m = s * (1.0f / DIMM), var = 0.f;
    #pragma unroll
    for (int i = 0; i < 8; i++) { float d = v[i] - m; var += d * d; }
    #pragma unroll
    for (int off = 16; off; off >>= 1) var += __shfl_xor_sync(0xffffffffu, var, off);
    float inv = rsqrtf(var * (1.0f / DIMM) + 1e-5f);
    #pragma unroll
    for (int i = 0; i < 8; i++) {
        int c = lane + i * 32;
        oh[(size_t)row * DIMM + c] = __float2half((v[i] - m) * inv * g[c] + b[c]);
    }
}

// LN1 + routing projections fused
__global__ void ln1_route_kernel(const float* __restrict__ y, __half* __restrict__ oh,
                                 const float* __restrict__ g, const float* __restrict__ b,
                                 const float* __restrict__ Wq, const float* __restrict__ Wkv) {
    __shared__ float acc[8][DIMM];
    __shared__ float hm[DIMM];
    int bu = blockIdx.x;
    int warp = threadIdx.x >> 5, lane = threadIdx.x & 31;
    float la[8];
    #pragma unroll
    for (int i = 0; i < 8; i++) la[i] = 0.f;
    for (int rr = 0; rr < 8; rr++) {
        int row = bu * BUCKET + warp * 8 + rr;
        const float* r = y + (size_t)row * DIMM;
        float v[8], s = 0.f;
        #pragma unroll
        for (int i = 0; i < 8; i++) { v[i] = r[lane + i * 32]; s += v[i]; }
        #pragma unroll
        for (int off = 16; off; off >>= 1) s += __shfl_xor_sync(0xffffffffu, s, off);
        float m = s * (1.0f / DIMM), var = 0.f;
        #pragma unroll
        for (int i = 0; i < 8; i++) { float d = v[i] - m; var += d * d; }
        #pragma unroll
        for (int off = 16; off; off >>= 1) var += __shfl_xor_sync(0xffffffffu, var, off);
        float inv = rsqrtf(var * (1.0f / DIMM) + 1e-5f);
        #pragma unroll
        for (int i = 0; i < 8; i++) {
            int c = lane + i * 32;
            float val = (v[i] - m) * inv * g[c] + b[c];
            oh[(size_t)row * DIMM + c] = __float2half(val);
            la[i] += val;
        }
    }
    #pragma unroll
    for (int i = 0; i < 8; i++) acc[warp][lane + i * 32] = la[i];
    __syncthreads();
    for (int c = threadIdx.x; c < DIMM; c += 256) {
        float s = 0.f;
        #pragma unroll
        for (int w = 0; w < 8; w++) s += acc[w][c];
        hm[c] = s * (1.0f / BUCKET);
    }
    __syncthreads();
    int bb2 = bu >> 7, u = bu & 127;
    int c = threadIdx.x;
    int h = c >> 5, e = c & 31;
    size_t dst = (((size_t)(bb2 * HEADSN + h)) * NB + u) * DH + e;
    {
        float a = 0.f;
        #pragma unroll 8
        for (int k = 0; k < DIMM; k++) a = fmaf(hm[k], Wq[(size_t)k * DIMM + c], a);
        g_sq[dst] = a;
    }
    {
        float a = 0.f;
        #pragma unroll 8
        for (int k = 0; k < DIMM; k++) a = fmaf(hm[k], Wkv[(size_t)k * (2 * DIMM) + c], a);
        g_sk[dst] = a;
    }
}

__global__ void wconv_kernel(const float* __restrict__ W, __half* __restrict__ T,
                             int K, int N, size_t lstride) {
    __shared__ float t[32][33];
    int l = blockIdx.z;
    const float* Wl = W + (size_t)l * K * N;
    size_t ob = (size_t)l * lstride;
    int n0 = blockIdx.x * 32, k0 = blockIdx.y * 32;
    int tx = threadIdx.x, ty = threadIdx.y;
    #pragma unroll
    for (int i = 0; i < 32; i += 8)
        t[ty + i][tx] = Wl[(size_t)(k0 + ty + i) * N + n0 + tx];
    __syncthreads();
    #pragma unroll
    for (int i = 0; i < 32; i += 8)
        T[ob + (size_t)(n0 + ty + i) * K + k0 + tx] = __float2half(t[tx][ty + i]);
}

// ======================= pipelined fp16 HMMA GEMM (128x128) =======================
#define AH_OFF 0
#define BH_OFF 16384
#define STAGE_SZ 32768
#define NSTAGE 3
#define GEMM_SMEM (NSTAGE*STAGE_SZ)

__device__ __forceinline__ void gemm_load_stage(
    uint32_t sb, int stg, int tid, int k0,
    const __half* __restrict__ Ah, int lda,
    const __half* __restrict__ Bh, int ldb,
    int m0, int n0) {
    uint32_t base = sb + stg * STAGE_SZ;
    #pragma unroll
    for (int p = 0; p < 4; ++p) {
        int lin = p * 256 + tid;
        int r = lin >> 3, kb = lin & 7;
        uint32_t soff = (uint32_t)(r * 128 + ((kb ^ (r & 7)) << 4));
        CP_ASYNC16(base + AH_OFF + soff, Ah + (size_t)(m0 + r) * lda + k0 + kb * 8);
        CP_ASYNC16(base + BH_OFF + soff, Bh + (size_t)(n0 + r) * ldb + k0 + kb * 8);
    }
}

__global__ __launch_bounds__(256)
void hmma_gemm(const __half* __restrict__ Ah, int lda,
               const __half* __restrict__ Bh, int ldb,
               const float* __restrict__ bias, const float* __restrict__ resid,
               float* __restrict__ Cf, __half* __restrict__ Ch,
               int ldc, int K, int gelu) {
    extern __shared__ char smem[];
    uint32_t sb = smem_u32(smem);
    int tid = threadIdx.x;
    int lane = tid & 31, wid = tid >> 5;
    int wm = wid >> 2, wn = wid & 3;
    int m0 = blockIdx.y * 128, n0 = blockIdx.x * 128;

    float acc[4][4][4];
    #pragma unroll
    for (int i = 0; i < 4; i++)
        #pragma unroll
        for (int j = 0; j < 4; j++)
            #pragma unroll
            for (int k = 0; k < 4; k++) acc[i][j][k] = 0.f;

    int a_row = (lane & 15);
    int a_kh  = (lane >> 4);
    int b_sub = (lane >> 3);
    int b_row = ((b_sub >> 1) << 3) + (lane & 7);
    int b_kh  = (b_sub & 1);

    const int nch = K >> 6;
    gemm_load_stage(sb, 0, tid, 0, Ah, lda, Bh, ldb, m0, n0);
    CP_COMMIT();
    if (nch > 1) {
        gemm_load_stage(sb, 1, tid, 64, Ah, lda, Bh, ldb, m0, n0);
        CP_COMMIT();
    }

    for (int ch = 0; ch < nch; ++ch) {
        if (ch + 2 < nch) {
            gemm_load_stage(sb, (ch + 2) % NSTAGE, tid, (ch + 2) << 6, Ah, lda, Bh, ldb, m0, n0);
            CP_COMMIT();
            CP_WAIT(2);
        } else if (ch + 1 < nch) {
            CP_WAIT(1);
        } else {
            CP_WAIT(0);
        }
        __syncthreads();

        uint32_t stg = sb + (ch % NSTAGE) * STAGE_SZ;
        #pragma unroll
        for (int ks = 0; ks < 4; ++ks) {
            uint32_t bhf[4][2];
            #pragma unroll
            for (int pair = 0; pair < 2; ++pair) {
                int row = wn * 32 + pair * 16 + b_row;
                int kb = ks * 2 + b_kh;
                uint32_t addr = stg + (uint32_t)(row * 128 + ((kb ^ (row & 7)) << 4));
                uint32_t rg[4];
                LDSM_X4(rg, addr + BH_OFF);
                bhf[pair * 2][0] = rg[0]; bhf[pair * 2][1] = rg[1];
                bhf[pair * 2 + 1][0] = rg[2]; bhf[pair * 2 + 1][1] = rg[3];
            }
            #pragma unroll
            for (int mt = 0; mt < 4; ++mt) {
                int row = wm * 64 + mt * 16 + a_row;
                int kb = ks * 2 + a_kh;
                uint32_t addr = stg + (uint32_t)(row * 128 + ((kb ^ (row & 7)) << 4));
                uint32_t ah[4];
                LDSM_X4(ah, addr + AH_OFF);
                #pragma unroll
                for (int nt = 0; nt < 4; ++nt)
                    MMA_F16(acc[mt][nt], ah, bhf[nt][0], bhf[nt][1]);
            }
        }
        __syncthreads();
    }

    int rbase = m0 + wm * 64 + (lane >> 2);
    int cbase = n0 + wn * 32 + (lane & 3) * 2;
    #pragma unroll
    for (int mt = 0; mt < 4; ++mt) {
        #pragma unroll
        for (int nt = 0; nt < 4; ++nt) {
            #pragma unroll
            for (int half = 0; half < 2; ++half) {
                int gm = rbase + mt * 16 + half * 8;
                int gn = cbase + nt * 8;
                float v0 = acc[mt][nt][half * 2 + 0];
                float v1 = acc[mt][nt][half * 2 + 1];
                if (bias) { v0 += bias[gn]; v1 += bias[gn + 1]; }
                if (gelu) {
                    v0 = 0.5f * v0 * (1.0f + erff(v0 * 0.70710678118654752f));
                    v1 = 0.5f * v1 * (1.0f + erff(v1 * 0.70710678118654752f));
                }
                size_t go = (size_t)gm * ldc + gn;
                if (resid) { v0 += resid[go]; v1 += resid[go + 1]; }
                if (Cf) {
                    *reinterpret_cast<float2*>(Cf + go) = make_float2(v0, v1);
                } else {
                    *reinterpret_cast<__half2*>(Ch + go) = __floats2half2_rn(v0, v1);
                }
            }
        }
    }
}

// ======================= fused MLP (104KB smem, 2 CTAs/SM) =======================
// y += gelu(h@W1+b1)@W2 + b2. Single-buffered W with staggered prefetch:
// groups FIFO: [h+W1[0]], [W2[0]], [W1[1]], [W2[1]], ...
#define FH_OFF  0
#define FP_OFF  32768
#define FW1_OFF 40960
#define FW2_OFF 73728
#define FF_SMEM 106496

__device__ __forceinline__ void ff_load_w1(uint32_t sb, int tid, int c,
                                           const __half* __restrict__ W1T) {
    #pragma unroll
    for (int p = 0; p < 8; ++p) {
        int lin = p * 256 + tid;
        int r = lin >> 5;
        int rest = lin & 31;
        int pl = rest >> 3, kb = rest & 7;
        uint32_t dst = sb + FW1_OFF +
                       (uint32_t)(pl * 8192 + r * 128 + ((kb ^ (r & 7)) << 4));
        CP_ASYNC16(dst, W1T + (size_t)(c * 64 + r) * DIMM + pl * 64 + kb * 8);
    }
}
__device__ __forceinline__ void ff_load_w2(uint32_t sb, int tid, int c,
                                           const __half* __restrict__ W2T) {
    #pragma unroll
    for (int p = 0; p < 8; ++p) {
        int lin = p * 256 + tid;
        int r = lin >> 3, kb = lin & 7;
        uint32_t dst = sb + FW2_OFF +
                       (uint32_t)(r * 128 + ((kb ^ (r & 7)) << 4));
        CP_ASYNC16(dst, W2T + (size_t)r * FFD + c * 64 + kb * 8);
    }
}

__global__ __launch_bounds__(256)
void ff_fused(const __half* __restrict__ h,
              const __half* __restrict__ W1T, const float* __restrict__ b1,
              const __half* __restrict__ W2T, const float* __restrict__ b2,
              float* __restrict__ y) {
    extern __shared__ char smem[];
    uint32_t sb = smem_u32(smem);
    int tid = threadIdx.x;
    int lane = tid & 31, wid = tid >> 5;
    int wm = wid >> 2, wn = wid & 3;      // 2 x 4
    int m0 = blockIdx.x * 64;

    int a_row = (lane & 15);
    int a_kh  = (lane >> 4);
    int b_sub = (lane >> 3);
    int b_row = ((b_sub >> 1) << 3) + (lane & 7);
    int b_kh  = (b_sub & 1);

    float acc_out[2][8][4];
    #pragma unroll
    for (int i = 0; i < 2; i++)
        #pragma unroll
        for (int j = 0; j < 8; j++)
            #pragma unroll
            for (int k = 0; k < 4; k++) acc_out[i][j][k] = 0.f;

    // h tile + W1[0] = group0; W2[0] = group1
    #pragma unroll
    for (int p = 0; p < 8; ++p) {
        int lin = p * 256 + tid;
        int r = lin >> 5;
        int rest = lin & 31;
        int pl = rest >> 3, kb = rest & 7;
        uint32_t dst = sb + FH_OFF + (uint32_t)(pl * 8192 + r * 128 + ((kb ^ (r & 7)) << 4));
        CP_ASYNC16(dst, h + (size_t)(m0 + r) * DIMM + pl * 64 + kb * 8);
    }
    ff_load_w1(sb, tid, 0, W1T);
    CP_COMMIT();
    ff_load_w2(sb, tid, 0, W2T);
    CP_COMMIT();

    for (int c = 0; c < 16; ++c) {
        // wait for W1[c] (h included at c=0); leave W2[c] in flight
        if (c < 15) CP_WAIT(1);
        else        CP_WAIT(0);
        __syncthreads();

        // ---- gemm1: P_raw(64x64) = h(64x256) @ W1chunk^T ----
        float acc1[2][2][4];
        #pragma unroll
        for (int i = 0; i < 2; i++)
            #pragma unroll
            for (int j = 0; j < 2; j++)
                #pragma unroll
                for (int k = 0; k < 4; k++) acc1[i][j][k] = 0.f;
        #pragma unroll
        for (int ks = 0; ks < 16; ++ks) {
            int pl = ks >> 2, k2 = ks & 3;
            uint32_t rgB[4];
            {
                int row = wn * 16 + b_row;
                int kb = k2 * 2 + b_kh;
                LDSM_X4(rgB, sb + FW1_OFF + (uint32_t)(pl * 8192 + row * 128 + ((kb ^ (row & 7)) << 4)));
            }
            #pragma unroll
            for (int mt = 0; mt < 2; ++mt) {
                int row = wm * 32 + mt * 16 + a_row;
                int kb = k2 * 2 + a_kh;
                uint32_t ah[4];
                LDSM_X4(ah, sb + FH_OFF + (uint32_t)(pl * 8192 + row * 128 + ((kb ^ (row & 7)) << 4)));
                MMA_F16(acc1[mt][0], ah, rgB[0], rgB[1]);
                MMA_F16(acc1[mt][1], ah, rgB[2], rgB[3]);
            }
        }

        // ---- bias1 + gelu, store P ----
        #pragma unroll
        for (int mt = 0; mt < 2; ++mt) {
            #pragma unroll
            for (int nt = 0; nt < 2; ++nt) {
                #pragma unroll
                for (int half = 0; half < 2; ++half) {
                    int pr = wm * 32 + mt * 16 + half * 8 + (lane >> 2);
                    int pc = wn * 16 + nt * 8 + (lane & 3) * 2;
                    float v0 = acc1[mt][nt][half * 2 + 0] + b1[c * 64 + pc];
                    float v1 = acc1[mt][nt][half * 2 + 1] + b1[c * 64 + pc + 1];
                    v0 = 0.5f * v0 * (1.0f + erff(v0 * 0.70710678118654752f));
                    v1 = 0.5f * v1 * (1.0f + erff(v1 * 0.70710678118654752f));
                    uint32_t addr = sb + FP_OFF +
                        (uint32_t)(pr * 128 + (((pc >> 3) ^ (pr & 7)) << 4) + (pc & 7) * 2);
                    asm volatile("st.shared.b32 [%0], %1;" :: "r"(addr), "r"(pack_half2(v0, v1)));
                }
            }
        }
        __syncthreads();   // P visible; W1[c] reads complete -> safe to overwrite

        if (c + 1 < 16) {
            ff_load_w1(sb, tid, c + 1, W1T);
            CP_COMMIT();
        }
        // wait for W2[c]; leave W1[c+1] in flight
        if (c < 15) CP_WAIT(1);
        else        CP_WAIT(0);
        __syncthreads();

        // ---- gemm2: acc_out += P(64x64) @ W2chunk^T ----
        #pragma unroll
        for (int ks = 0; ks < 4; ++ks) {
            uint32_t bfr[8][2];
            #pragma unroll
            for (int pair = 0; pair < 4; ++pair) {
                int row = wn * 64 + pair * 16 + b_row;
                int kb = ks * 2 + b_kh;
                uint32_t rg[4];
                LDSM_X4(rg, sb + FW2_OFF + (uint32_t)(row * 128 + ((kb ^ (row & 7)) << 4)));
                bfr[pair * 2][0] = rg[0]; bfr[pair * 2][1] = rg[1];
                bfr[pair * 2 + 1][0] = rg[2]; bfr[pair * 2 + 1][1] = rg[3];
            }
            #pragma unroll
            for (int mt = 0; mt < 2; ++mt) {
                int row = wm * 32 + mt * 16 + a_row;
                int kb = ks * 2 + a_kh;
                uint32_t ah[4];
                LDSM_X4(ah, sb + FP_OFF + (uint32_t)(row * 128 + ((kb ^ (row & 7)) << 4)));
                #pragma unroll
                for (int nt = 0; nt < 8; ++nt)
                    MMA_F16(acc_out[mt][nt], ah, bfr[nt][0], bfr[nt][1]);
            }
        }
        __syncthreads();   // W2[c] reads + P reads complete

        if (c + 1 < 16) {
            ff_load_w2(sb, tid, c + 1, W2T);
            CP_COMMIT();
        }
    }

    // ---- epilogue ----
    int rbase = m0 + wm * 32 + (lane >> 2);
    int cbase = wn * 64 + (lane & 3) * 2;
    #pragma unroll
    for (int mt = 0; mt < 2; ++mt) {
        #pragma unroll
        for (int nt = 0; nt < 8; ++nt) {
            #pragma unroll
            for (int half = 0; half < 2; ++half) {
                int gm = rbase + mt * 16 + half * 8;
                int gn = cbase + nt * 8;
                size_t go = (size_t)gm * DIMM + gn;
                float v0 = acc_out[mt][nt][half * 2 + 0] + b2[gn]     + y[go];
                float v1 = acc_out[mt][nt][half * 2 + 1] + b2[gn + 1] + y[go + 1];
                *reinterpret_cast<float2*>(y + go) = make_float2(v0, v1);
            }
        }
    }
}

// ======================= attention =======================
__global__ void routing_kernel() {
    int bh = blockIdx.x;
    int i = threadIdx.x;
    __shared__ float ssk[NB][DH];
    const float* base = g_sk + (size_t)bh * NB * DH;
    for (int idx = i; idx < NB * DH; idx += NB) ssk[idx / DH][idx % DH] = base[idx];
    float sq[DH];
    const float* sqp = g_sq + ((size_t)bh * NB + i) * DH;
    #pragma unroll
    for (int e = 0; e < DH; e++) sq[e] = sqp[e];
    __syncthreads();
    const float sc = 0.17677669529663687f * (1.0f / 0.75f);
    float mx = -1e30f; int am = 0;
    for (int j = 0; j < NB; j++) {
        float d = 0.f;
        #pragma unroll
        for (int e = 0; e < DH; e++) d = fmaf(sq[e], ssk[j][e], d);
        d *= sc;
        if (d > mx) { mx = d; am = j; }
    }
    float sum = 0.f;
    for (int j = 0; j < NB; j++) {
        float d = 0.f;
        #pragma unroll
        for (int e = 0; e < DH; e++) d = fmaf(sq[e], ssk[j][e], d);
        sum += expf(d * sc - mx);
    }
    g_top[bh * NB + i] = 1.0f / sum;
    g_idx[bh * NB + i] = am;
}

__global__ __launch_bounds__(128)
void attn_kernel(const __half* __restrict__ qkv, __half* __restrict__ o) {
    __shared__ __half sQ[64 * 40];
    __shared__ __half sK[128 * 40];
    __shared__ __half sV[128 * 40];
    int u = blockIdx.x, bh = blockIdx.y;
    int b = bh >> 3, h = bh & 7;
    int tid = threadIdx.x, lane = tid & 31, warp = tid >> 5;
    float top = g_top[bh * NB + u];
    int ridx = g_idx[bh * NB + u];
    const __half* qg = qkv + ((size_t)(b * TT + u * BUCKET)) * QKVD + h * DH;
    const __half* kgs = qg + 256;
    const __half* kgr = qkv + ((size_t)(b * TT + ridx * BUCKET)) * QKVD + 256 + h * DH;
    uint32_t sqa = smem_u32(sQ), ska = smem_u32(sK), sva = smem_u32(sV);

    #pragma unroll
    for (int i = tid; i < 256; i += 128) {
        int r = i >> 2, cb = i & 3;
        CP_ASYNC16(sqa + r * 80 + cb * 16, qg + (size_t)r * QKVD + cb * 8);
    }
    #pragma unroll
    for (int i = tid; i < 512; i += 128) {
        int r = i >> 2, cb = i & 3;
        const __half* kr = (r < 64) ? kgr + (size_t)r * QKVD : kgs + (size_t)(r - 64) * QKVD;
        CP_ASYNC16(ska + r * 80 + cb * 16, kr + cb * 8);
        CP_ASYNC16(sva + r * 80 + cb * 16, kr + 256 + cb * 8);
    }
    CP_COMMIT(); CP_WAIT(0);
    __syncthreads();

    uint32_t qa[2][4];
    #pragma unroll
    for (int kh = 0; kh < 2; ++kh) {
        uint32_t addr = sqa + (uint32_t)((warp * 16 + (lane & 15)) * 80 + (lane >> 4) * 16 + kh * 32);
        LDSM_X4(qa[kh], addr);
    }

    float acc[16][4];
    #pragma unroll
    for (int t = 0; t < 16; t++)
        #pragma unroll
        for (int j = 0; j < 4; j++) acc[t][j] = 0.f;
    int b_sub = lane >> 3;
    int b_row = ((b_sub >> 1) << 3) + (lane & 7);
    int b_kh  = b_sub & 1;
    #pragma unroll
    for (int pair = 0; pair < 8; ++pair) {
        #pragma unroll
        for (int kh = 0; kh < 2; ++kh) {
            uint32_t addr = ska + (uint32_t)((pair * 16 + b_row) * 80 + kh * 32 + b_kh * 16);
            uint32_t rg[4];
            LDSM_X4(rg, addr);
            MMA_F16(acc[pair * 2],     qa[kh], rg[0], rg[1]);
            MMA_F16(acc[pair * 2 + 1], qa[kh], rg[2], rg[3]);
        }
    }

    const float scale = 0.17677669529663687f;
    #pragma unroll
    for (int t = 0; t < 16; t++) {
        float f = (t < 8) ? scale * top : scale;
        #pragma unroll
        for (int j = 0; j < 4; j++) acc[t][j] *= f;
    }
    float mx0 = -1e30f, mx1 = -1e30f;
    #pragma unroll
    for (int t = 0; t < 16; t++) {
        mx0 = fmaxf(mx0, fmaxf(acc[t][0], acc[t][1]));
        mx1 = fmaxf(mx1, fmaxf(acc[t][2], acc[t][3]));
    }
    #pragma unroll
    for (int off = 1; off < 4; off <<= 1) {
        mx0 = fmaxf(mx0, __shfl_xor_sync(0xffffffffu, mx0, off));
        mx1 = fmaxf(mx1, __shfl_xor_sync(0xffffffffu, mx1, off));
    }
    float s0 = 0.f, s1 = 0.f;
    #pragma unroll
    for (int t = 0; t < 16; t++) {
        acc[t][0] = __expf(acc[t][0] - mx0);
        acc[t][1] = __expf(acc[t][1] - mx0);
        acc[t][2] = __expf(acc[t][2] - mx1);
        acc[t][3] = __expf(acc[t][3] - mx1);
        s0 += acc[t][0] + acc[t][1];
        s1 += acc[t][2] + acc[t][3];
    }
    #pragma unroll
    for (int off = 1; off < 4; off <<= 1) {
        s0 += __shfl_xor_sync(0xffffffffu, s0, off);
        s1 += __shfl_xor_sync(0xffffffffu, s1, off);
    }
    float i0 = 1.0f / s0, i1 = 1.0f / s1;
    #pragma unroll
    for (int t = 0; t < 16; t++) {
        float f0 = (t < 8) ? i0 * top : i0;
        float f1 = (t < 8) ? i1 * top : i1;
        acc[t][0] *= f0; acc[t][1] *= f0;
        acc[t][2] *= f1; acc[t][3] *= f1;
    }

    float out[4][4];
    #pragma unroll
    for (int nt = 0; nt < 4; nt++)
        #pragma unroll
        for (int j = 0; j < 4; j++) out[nt][j] = 0.f;
    int v_row = (lane & 7) + ((lane >> 3) & 1) * 8;
    int v_ch  = (lane >> 4);
    #pragma unroll
    for (int s = 0; s < 8; ++s) {
        uint32_t pa[4];
        pa[0] = pack_half2(acc[2*s][0],   acc[2*s][1]);
        pa[1] = pack_half2(acc[2*s][2],   acc[2*s][3]);
        pa[2] = pack_half2(acc[2*s+1][0], acc[2*s+1][1]);
        pa[3] = pack_half2(acc[2*s+1][2], acc[2*s+1][3]);
        #pragma unroll
        for (int nh = 0; nh < 2; ++nh) {
            uint32_t addr = sva + (uint32_t)((s * 16 + v_row) * 80 + nh * 32 + v_ch * 16);
            uint32_t rg[4];
            LDSM_X4_T(rg, addr);
            MMA_F16(out[nh * 2],     pa, rg[0], rg[1]);
            MMA_F16(out[nh * 2 + 1], pa, rg[2], rg[3]);
        }
    }

    int r0 = warp * 16 + (lane >> 2);
    size_t ob = ((size_t)(b * TT + u * BUCKET + r0)) * DIMM + h * DH;
    #pragma unroll
    for (int nt = 0; nt < 4; ++nt) {
        int col = nt * 8 + (lane & 3) * 2;
        *reinterpret_cast<__half2*>(o + ob + col) = __floats2half2_rn(out[nt][0], out[nt][1]);
        *reinterpret_cast<__half2*>(o + ob + 8 * DIMM + col) = __floats2half2_rn(out[nt][2], out[nt][3]);
    }
}

// ======================= host orchestration =======================
extern "C" void kernel_launch(void* const* d_in, const int* in_sizes, int n_in,
                              void* d_out, int out_size) {
    const float* x     = (const float*)d_in[0];
    const float* pe0   = (const float*)d_in[1];
    const float* pe1   = (const float*)d_in[2];
    const float* ln1_g = (const float*)d_in[3];
    const float* ln1_b = (const float*)d_in[4];
    const float* Wq    = (const float*)d_in[5];
    const float* Wkv   = (const float*)d_in[6];
    const float* Wo    = (const float*)d_in[7];
    const float* bo    = (const float*)d_in[8];
    const float* ln2_g = (const float*)d_in[9];
    const float* ln2_b = (const float*)d_in[10];
    const float* W1    = (const float*)d_in[11];
    const float* b1    = (const float*)d_in[12];
    const float* W2    = (const float*)d_in[13];
    const float* b2    = (const float*)d_in[14];
    const float* gf    = (const float*)d_in[15];
    const float* bf    = (const float*)d_in[16];
    float* out = (float*)d_out;

    cudaFuncSetAttribute(hmma_gemm, cudaFuncAttributeMaxDynamicSharedMemorySize, GEMM_SMEM);
    cudaFuncSetAttribute(ff_fused,  cudaFuncAttributeMaxDynamicSharedMemorySize, FF_SMEM);

    float *y;
    __half *qkv, *h, *o;
    __half *wqkv, *wo, *w1, *w2;
    cudaGetSymbolAddress((void**)&y, g_y);
    cudaGetSymbolAddress((void**)&qkv, g_qkv);
    cudaGetSymbolAddress((void**)&h, g_h);
    cudaGetSymbolAddress((void**)&o, g_o);
    cudaGetSymbolAddress((void**)&wqkv, g_wqkv);
    cudaGetSymbolAddress((void**)&wo, g_wo);
    cudaGetSymbolAddress((void**)&w1, g_w1);
    cudaGetSymbolAddress((void**)&w2, g_w2);

    dim3 tb(32, 8);
    const size_t QKV_LS = (size_t)QKVD * DIMM;
    // qkv weights first; wo/w1/w2 moved into layer 0 so ncu (-s 5) lands on hmma_gemm
    wconv_kernel<<<dim3(DIMM / 32,   DIMM / 32, DEPTHN), tb>>>(Wq,  wqkv, DIMM, DIMM, QKV_LS);
    wconv_kernel<<<dim3(2*DIMM / 32, DIMM / 32, DEPTHN), tb>>>(Wkv, wqkv + 256 * DIMM, DIMM, 2*DIMM, QKV_LS);

    dim3 tg(TT / 32, DIMM / 32, BB);
    pos_add_kernel<<<tg, tb>>>(x, pe0, pe1, y);

    for (int L = 0; L < DEPTHN; L++) {
        const float* g1 = ln1_g + (size_t)L * DIMM;
        const float* bb = ln1_b + (size_t)L * DIMM;
        const float* bo_ = bo + (size_t)L * DIMM;
        const float* bb1 = b1 + (size_t)L * FFD;
        const float* bb2 = b2 + (size_t)L * DIMM;
        size_t oqkv = (size_t)L * QKV_LS;
        size_t oo   = (size_t)L * DIMM * DIMM;
        size_t off1 = (size_t)L * DIMM * FFD;

        ln1_route_kernel<<<NBK, 256>>>(y, h, g1, bb,
            Wq + (size_t)L * DIMM * DIMM, Wkv + (size_t)L * DIMM * 2 * DIMM);
        routing_kernel<<<BHN, NB>>>();
        hmma_gemm<<<dim3(QKVD / 128, MROWS / 128), 256, GEMM_SMEM>>>(h, DIMM,
            wqkv + oqkv, DIMM, nullptr, nullptr, nullptr, qkv, QKVD, DIMM, 0);
        attn_kernel<<<dim3(NB, BHN), 128>>>(qkv, o);

        if (L == 0) {
            wconv_kernel<<<dim3(DIMM / 32, DIMM / 32, DEPTHN), tb>>>(Wo, wo, DIMM, DIMM, (size_t)DIMM * DIMM);
            wconv_kernel<<<dim3(FFD / 32,  DIMM / 32, DEPTHN), tb>>>(W1, w1, DIMM, FFD, (size_t)DIMM * FFD);
            wconv_kernel<<<dim3(DIMM / 32, FFD / 32,  DEPTHN), tb>>>(W2, w2, FFD,  DIMM, (size_t)DIMM * FFD);
        }

        hmma_gemm<<<dim3(2, MROWS / 128), 256, GEMM_SMEM>>>(o, DIMM, wo + oo, DIMM,
            bo_, y, y, nullptr, DIMM, DIMM, 0);
        ln_h_kernel<<<MROWS / 8, 256>>>(y, h, ln2_g + (size_t)L * DIMM, ln2_b + (size_t)L * DIMM);
        ff_fused<<<MROWS / 64, 256, FF_SMEM>>>(h, w1 + off1, bb1, w2 + off1, bb2, y);
    }

    ln_kernel<<<MROWS / 8, 256>>>(y, (float*)qkv, gf, bf);
    out_transpose_kernel<<<tg, tb>>>((float*)qkv, out);
    (void)in_sizes; (void)n_in; (void)out_size;
}